// round 7
// baseline (speedup 1.0000x reference)
#include <cuda_runtime.h>
#include <cuda_bf16.h>
#include <cstdint>

// Problem constants
#define B_    4
#define T_    1024
#define C_    512
#define V_    4096
#define H_    8
#define Q_    256
#define MFULL 4096
#define MREST 1024
#define MTOT  5120
#define ZHAT_ELEMS (B_*C_*T_)
#define COMB_SCALE 0.044194173824159216f

// ---- scratch ----
__device__ float g_hs[MFULL*C_];
__device__ float g_Xq[MFULL*C_];
__device__ float g_Xp[MFULL*H_];
__device__ float g_value[V_*C_];
__device__ float g_kh[V_*C_];
__device__ float g_Q[MTOT*C_];
__device__ __nv_bfloat16 g_Qh[MTOT*C_];
__device__ __nv_bfloat16 g_Kh[V_*C_];
__device__ float g_logits[(size_t)MTOT*V_];
__device__ float g_qnorm[MTOT];
__device__ int   g_knmax_i;
__device__ int   g_idx[MTOT];
__device__ int   g_cnt[V_];

// =====================  mma / ldmatrix helpers  =====================
#define MMA_TF32(c, a, b0, b1) \
    asm volatile("mma.sync.aligned.m16n8k8.row.col.f32.tf32.tf32.f32 " \
        "{%0,%1,%2,%3}, {%4,%5,%6,%7}, {%8,%9}, {%0,%1,%2,%3};" \
        : "+f"((c)[0]), "+f"((c)[1]), "+f"((c)[2]), "+f"((c)[3]) \
        : "r"((a)[0]), "r"((a)[1]), "r"((a)[2]), "r"((a)[3]), "r"(b0), "r"(b1))

#define MMA_BF16(c, a, b0, b1) \
    asm volatile("mma.sync.aligned.m16n8k16.row.col.f32.bf16.bf16.f32 " \
        "{%0,%1,%2,%3}, {%4,%5,%6,%7}, {%8,%9}, {%0,%1,%2,%3};" \
        : "+f"((c)[0]), "+f"((c)[1]), "+f"((c)[2]), "+f"((c)[3]) \
        : "r"((a)[0]), "r"((a)[1]), "r"((a)[2]), "r"((a)[3]), "r"(b0), "r"(b1))

#define LDSM_X4(r0, r1, r2, r3, addr) \
    asm volatile("ldmatrix.sync.aligned.m8n8.x4.shared.b16 {%0,%1,%2,%3}, [%4];" \
        : "=r"(r0), "=r"(r1), "=r"(r2), "=r"(r3) : "r"(addr))

__device__ __forceinline__ uint32_t tf32_of(float x) {
    uint32_t r; asm("cvt.rna.tf32.f32 %0, %1;" : "=r"(r) : "f"(x)); return r;
}
#define SPLIT4(vh, vl, v) do { \
    (vh).x = tf32_of((v).x); (vl).x = tf32_of((v).x - __uint_as_float((vh).x)); \
    (vh).y = tf32_of((v).y); (vl).y = tf32_of((v).y - __uint_as_float((vh).y)); \
    (vh).z = tf32_of((v).z); (vl).z = tf32_of((v).z - __uint_as_float((vh).z)); \
    (vh).w = tf32_of((v).w); (vl).w = tf32_of((v).w - __uint_as_float((vh).w)); \
} while (0)

// =====================  small kernels  =====================
__global__ void k_init() {
    int i = blockIdx.x * blockDim.x + threadIdx.x;
    if (i < V_) g_cnt[i] = 0;
    if (i == 0) g_knmax_i = 0;
}

__global__ void k_transpose(const float* __restrict__ z) {
    __shared__ float tile[32][33];
    int b = blockIdx.z, c0 = blockIdx.x << 5, t0 = blockIdx.y << 5;
    int tx = threadIdx.x, ty = threadIdx.y;
#pragma unroll
    for (int j = 0; j < 4; j++)
        tile[ty + 8*j][tx] = z[(b*C_ + c0 + ty + 8*j)*T_ + t0 + tx];
    __syncthreads();
#pragma unroll
    for (int j = 0; j < 4; j++)
        g_hs[(b*T_ + t0 + ty + 8*j)*C_ + c0 + tx] = tile[tx][ty + 8*j];
}

__global__ __launch_bounds__(256) void k_xp(const float* __restrict__ Wp,
                                            const float* __restrict__ bp) {
    __shared__ float w[C_ * H_];
    int tid = threadIdx.x;
    for (int i = tid * 4; i < C_ * H_; i += 1024)
        *(float4*)&w[i] = *(const float4*)&Wp[i];
    __syncthreads();
    int row = blockIdx.x * 256 + tid;
    const float* hsr = g_hs + (size_t)row * C_;
    float acc[8];
#pragma unroll
    for (int j = 0; j < 8; j++) acc[j] = bp[j];
#pragma unroll 4
    for (int k = 0; k < C_; k += 4) {
        float4 hv = *(const float4*)(hsr + k);
        float h[4] = {hv.x, hv.y, hv.z, hv.w};
#pragma unroll
        for (int i = 0; i < 4; i++) {
            float4 wa = *(const float4*)&w[(k + i) * 8];
            float4 wb = *(const float4*)&w[(k + i) * 8 + 4];
            acc[0] += h[i] * wa.x; acc[1] += h[i] * wa.y;
            acc[2] += h[i] * wa.z; acc[3] += h[i] * wa.w;
            acc[4] += h[i] * wb.x; acc[5] += h[i] * wb.y;
            acc[6] += h[i] * wb.z; acc[7] += h[i] * wb.w;
        }
    }
    *(float4*)(g_Xp + row * 8)     = make_float4(acc[0], acc[1], acc[2], acc[3]);
    *(float4*)(g_Xp + row * 8 + 4) = make_float4(acc[4], acc[5], acc[6], acc[7]);
}

// =====================  split-tf32 projection GEMM with ldmatrix  =====================
// Fragment-linear smem: chunk(unit, lane) at byte (unit*33 + lane)*16, unit stride
// 33 chunks (528B) to de-alias store banks.  16 units per tile (A and B).
// A unit = ((warpM*2 + mt)*2 + ks8); lane = (half + 2*kc)*8 + r8.
// B unit = ((warpN*4 + ntp)*2 + ks8); lane = (ng1*2 + kc)*8 + n8.
#define TBUF 8448                  // 16 units * 33 chunks * 16B
#define OFF_AH 0
#define OFF_AL (2*TBUF)
#define OFF_BH (4*TBUF)
#define OFF_BL (6*TBUF)
#define PROJ_SMEM (8*TBUF)         // 67584 B

__global__ __launch_bounds__(256, 2) void k_proj_mma(
    const float* __restrict__ cb,
    const float* __restrict__ Wq, const float* __restrict__ bq,
    const float* __restrict__ Wk, const float* __restrict__ bk,
    const float* __restrict__ Wv, const float* __restrict__ bv) {
    extern __shared__ __align__(16) unsigned char smraw[];
    const uint32_t smb = (uint32_t)__cvta_generic_to_shared(smraw);

    const float *A, *Bm, *bias; float* C;
    int zid = blockIdx.z;
    if (zid == 0)      { A = g_hs; Bm = Wq; bias = bq; C = g_Xq; }
    else if (zid == 1) { A = cb;   Bm = Wk; bias = bk; C = g_kh; }
    else               { A = cb;   Bm = Wv; bias = bv; C = g_value; }

    const int tid = threadIdx.x;
    const int wid = tid >> 5, lane = tid & 31;
    const int warpM = wid >> 1, warpN = wid & 1;
    const int m0 = blockIdx.y << 7, n0 = blockIdx.x << 7;
    const int ar = tid >> 2, ac = (tid & 3) << 2;   // A: row ar(+64), k words ac..ac+3
    const int br = tid >> 4, bc = (tid & 15) << 3;  // B: k=br, n cols bc..bc+7
    const int gid = lane >> 2, tig = lane & 3;

    // ---- writer byte offsets (constant per thread) ----
    // A row ar, chunk (ks8 = ac>>3, kc = (ac>>2)&1):
    const int a_unit = (((ar >> 5) * 2 + ((ar >> 4) & 1)) * 2 + (ac >> 3));
    const int a_lane = ((((ar >> 3) & 1) + (((ac >> 2) & 1) << 1)) << 3) + (ar & 7);
    const uint32_t a_off = (uint32_t)(a_unit * 33 + a_lane) * 16;
    // row ar+64: warpM += 2 -> unit += 8 -> +8*528 bytes
    const uint32_t a_off2 = a_off + 8 * 528;
    // B word (k=br, n=bc+j):
    const int b_kc = (br >> 2) & 1, b_kw = br & 3, b_ks8 = br >> 3;
    // per-j byte offset computed in loop

    const float* Ap = A  + (size_t)(m0 + ar) * C_ + ac;
    const float* Bp = Bm + (size_t)br * 512 + n0 + bc;

    // ---- fill buffer 0 ----
    {
        float4 va0 = *(const float4*)Ap;
        float4 va1 = *(const float4*)(Ap + 64 * C_);
        float4 vb0 = *(const float4*)Bp;
        float4 vb1 = *(const float4*)(Bp + 4);
        uint4 h, l;
        SPLIT4(h, l, va0);
        *(uint4*)(smraw + OFF_AH + a_off)  = h; *(uint4*)(smraw + OFF_AL + a_off)  = l;
        SPLIT4(h, l, va1);
        *(uint4*)(smraw + OFF_AH + a_off2) = h; *(uint4*)(smraw + OFF_AL + a_off2) = l;
        float vj[8] = {vb0.x, vb0.y, vb0.z, vb0.w, vb1.x, vb1.y, vb1.z, vb1.w};
#pragma unroll
        for (int j = 0; j < 8; j++) {
            int n = bc + j;
            int unit = (n >> 4) * 2 + b_ks8;
            int L = ((((n >> 3) & 1) * 2 + b_kc) << 3) + j;
            uint32_t off = (uint32_t)((unit * 33 + L) * 4 + b_kw) * 4;
            uint32_t hv = tf32_of(vj[j]);
            uint32_t lv = tf32_of(vj[j] - __uint_as_float(hv));
            *(uint32_t*)(smraw + OFF_BH + off) = hv;
            *(uint32_t*)(smraw + OFF_BL + off) = lv;
        }
    }
    __syncthreads();

    float acc[2][8][4] = {};
    for (int t = 0; t < 32; ++t) {
        const int cur = t & 1;
        const uint32_t bufo = (uint32_t)cur * TBUF;
        float4 pa0, pa1, pb0, pb1;
        if (t < 31) {
            const float* A2 = Ap + (t + 1) * 16;
            const float* B2 = Bp + (size_t)(t + 1) * 16 * 512;
            pa0 = *(const float4*)A2;
            pa1 = *(const float4*)(A2 + 64 * C_);
            pb0 = *(const float4*)B2;
            pb1 = *(const float4*)(B2 + 4);
        }
        const uint32_t aH = smb + OFF_AH + bufo, aL = smb + OFF_AL + bufo;
        const uint32_t bH = smb + OFF_BH + bufo, bL = smb + OFF_BL + bufo;
#pragma unroll
        for (int ks8 = 0; ks8 < 2; ks8++) {
            uint32_t ah[2][4], al[2][4];
#pragma unroll
            for (int mt = 0; mt < 2; mt++) {
                uint32_t u = (uint32_t)(((warpM * 2 + mt) * 2 + ks8) * 528 + lane * 16);
                LDSM_X4(ah[mt][0], ah[mt][1], ah[mt][2], ah[mt][3], aH + u);
                LDSM_X4(al[mt][0], al[mt][1], al[mt][2], al[mt][3], aL + u);
            }
#pragma unroll
            for (int ntp = 0; ntp < 4; ntp++) {
                uint32_t u = (uint32_t)((((warpN * 4 + ntp) * 2) + ks8) * 528 + lane * 16);
                uint32_t bh[4], bl[4];
                LDSM_X4(bh[0], bh[1], bh[2], bh[3], bH + u);
                LDSM_X4(bl[0], bl[1], bl[2], bl[3], bL + u);
                const int nt0 = ntp * 2, nt1 = nt0 + 1;
#pragma unroll
                for (int mt = 0; mt < 2; mt++) {
                    MMA_TF32(acc[mt][nt0], ah[mt], bh[0], bh[1]);
                    MMA_TF32(acc[mt][nt0], ah[mt], bl[0], bl[1]);
                    MMA_TF32(acc[mt][nt0], al[mt], bh[0], bh[1]);
                    MMA_TF32(acc[mt][nt1], ah[mt], bh[2], bh[3]);
                    MMA_TF32(acc[mt][nt1], ah[mt], bl[2], bl[3]);
                    MMA_TF32(acc[mt][nt1], al[mt], bh[2], bh[3]);
                }
            }
        }
        if (t < 31) {
            const uint32_t nb = (uint32_t)(cur ^ 1) * TBUF;
            uint4 h, l;
            SPLIT4(h, l, pa0);
            *(uint4*)(smraw + OFF_AH + nb + a_off)  = h; *(uint4*)(smraw + OFF_AL + nb + a_off)  = l;
            SPLIT4(h, l, pa1);
            *(uint4*)(smraw + OFF_AH + nb + a_off2) = h; *(uint4*)(smraw + OFF_AL + nb + a_off2) = l;
            float vj[8] = {pb0.x, pb0.y, pb0.z, pb0.w, pb1.x, pb1.y, pb1.z, pb1.w};
#pragma unroll
            for (int j = 0; j < 8; j++) {
                int n = bc + j;
                int unit = (n >> 4) * 2 + b_ks8;
                int L = ((((n >> 3) & 1) * 2 + b_kc) << 3) + j;
                uint32_t off = (uint32_t)((unit * 33 + L) * 4 + b_kw) * 4;
                uint32_t hv = tf32_of(vj[j]);
                uint32_t lv = tf32_of(vj[j] - __uint_as_float(hv));
                *(uint32_t*)(smraw + OFF_BH + nb + off) = hv;
                *(uint32_t*)(smraw + OFF_BL + nb + off) = lv;
            }
            __syncthreads();
        }
    }

#pragma unroll
    for (int mt = 0; mt < 2; mt++) {
#pragma unroll
        for (int nt = 0; nt < 8; nt++) {
            int row = m0 + warpM * 32 + mt * 16 + gid;
            int col = n0 + warpN * 64 + nt * 8 + 2 * tig;
            float b0 = bias[col], b1 = bias[col + 1];
            float2 v0 = make_float2(acc[mt][nt][0] + b0, acc[mt][nt][1] + b1);
            float2 v1 = make_float2(acc[mt][nt][2] + b0, acc[mt][nt][3] + b1);
            *(float2*)(C + (size_t)row * C_ + col)       = v0;
            *(float2*)(C + (size_t)(row + 8) * C_ + col) = v1;
        }
    }
}

// =====================  rmsnorm + combine kernels  =====================
__device__ __forceinline__ float head_rms_scale(float x, int d, float* ws) {
    float s = x * x;
#pragma unroll
    for (int o = 16; o; o >>= 1) s += __shfl_xor_sync(0xffffffffu, s, o);
    if ((d & 31) == 0) ws[d >> 5] = s;
    __syncthreads();
    int h = d >> 6;
    float tot = ws[2*h] + ws[2*h + 1];
    return rsqrtf(tot * (1.0f/64.0f) + 1e-5f);
}

__device__ __forceinline__ float block_sum_sq(float v, int d, float* s2) {
    float s = v * v;
#pragma unroll
    for (int o = 16; o; o >>= 1) s += __shfl_xor_sync(0xffffffffu, s, o);
    if ((d & 31) == 0) s2[d >> 5] = s;
    __syncthreads();
    float tot = 0.0f;
    if (d == 0) {
#pragma unroll
        for (int i = 0; i < 16; i++) tot += s2[i];
    }
    return tot;
}

__global__ void k_khnorm(const float* __restrict__ gk) {
    __shared__ float ws[16];
    __shared__ float s2[16];
    int row = blockIdx.x, d = threadIdx.x;
    float x = g_kh[(size_t)row*C_ + d];
    float r = head_rms_scale(x, d, ws);
    float v = x * r * gk[d & 63];
    g_kh[(size_t)row*C_ + d] = v;
    g_Kh[(size_t)row*C_ + d] = __float2bfloat16(v);
    __syncthreads();
    float n2 = block_sum_sq(v, d, s2);
    if (d == 0) atomicMax(&g_knmax_i, __float_as_int(sqrtf(n2)));
}

__global__ void k_qfull(const float* __restrict__ gq) {
    __shared__ float ws[16];
    __shared__ float s2[16];
    int row = blockIdx.x, d = threadIdx.x, h = d >> 6;
    float x = g_Xq[(size_t)row*C_ + d];
    float r = head_rms_scale(x, d, ws);
    float c = g_Xp[row*H_ + h];
    float v = x * r * gq[d & 63] * c * COMB_SCALE;
    g_Q[(size_t)row*C_ + d] = v;
    g_Qh[(size_t)row*C_ + d] = __float2bfloat16(v);
    __syncthreads();
    float n2 = block_sum_sq(v, d, s2);
    if (d == 0) g_qnorm[row] = sqrtf(n2);
}

__global__ void k_qrest(const float* __restrict__ gq) {
    __shared__ float ws[16];
    __shared__ float s2[16];
    int row = blockIdx.x, d = threadIdx.x, h = d >> 6;
    int fr = (row >> 8) * T_ + (row & 255) * 4;
    const float* p = g_Xq + (size_t)fr*C_ + d;
    float x = 0.25f * (p[0] + p[C_] + p[2*C_] + p[3*C_]);
    float r = head_rms_scale(x, d, ws);
    const float* pc = g_Xp + fr*H_ + h;
    float c = 0.25f * (pc[0] + pc[H_] + pc[2*H_] + pc[3*H_]);
    float v = x * r * gq[d & 63] * c * COMB_SCALE;
    g_Q[(size_t)(MFULL + row)*C_ + d] = v;
    g_Qh[(size_t)(MFULL + row)*C_ + d] = __float2bfloat16(v);
    __syncthreads();
    float n2 = block_sum_sq(v, d, s2);
    if (d == 0) g_qnorm[MFULL + row] = sqrtf(n2);
}

// =====================  bf16 mma.sync logits GEMM (NT)  =====================
#define LPAD 20

__global__ __launch_bounds__(256, 2) void k_logits_mma() {
    __shared__ uint32_t As[2][128][LPAD];
    __shared__ uint32_t Bs[2][128][LPAD];
    const int tid = threadIdx.x;
    const int wid = tid >> 5, lane = tid & 31;
    const int warpM = wid >> 1, warpN = wid & 1;
    const int m0 = blockIdx.y << 7, n0 = blockIdx.x << 7;
    const int gid = lane >> 2, tig = lane & 3;
    const int row = tid >> 1, hf = tid & 1;

    const uint4* Ag = (const uint4*)(g_Qh + (size_t)(m0 + row) * C_) + hf * 2;
    const uint4* Bg = (const uint4*)(g_Kh + (size_t)(n0 + row) * C_) + hf * 2;

    {
        uint4 a0 = Ag[0], a1 = Ag[1];
        uint4 b0 = Bg[0], b1 = Bg[1];
        *(uint4*)&As[0][row][hf*8]     = a0;
        *(uint4*)&As[0][row][hf*8 + 4] = a1;
        *(uint4*)&Bs[0][row][hf*8]     = b0;
        *(uint4*)&Bs[0][row][hf*8 + 4] = b1;
    }
    __syncthreads();

    float acc[2][8][4] = {};
    for (int t = 0; t < 16; ++t) {
        const int cur = t & 1;
        uint4 pa0, pa1, pb0, pb1;
        if (t < 15) {
            const uint4* A2 = Ag + (t + 1) * 4;
            const uint4* B2 = Bg + (t + 1) * 4;
            pa0 = A2[0]; pa1 = A2[1];
            pb0 = B2[0]; pb1 = B2[1];
        }
#pragma unroll
        for (int ku = 0; ku < 16; ku += 8) {
            uint32_t af[2][4];
#pragma unroll
            for (int mt = 0; mt < 2; mt++) {
                int r = warpM * 32 + mt * 16 + gid;
                af[mt][0] = As[cur][r][ku + tig];
                af[mt][1] = As[cur][r + 8][ku + tig];
                af[mt][2] = As[cur][r][ku + tig + 4];
                af[mt][3] = As[cur][r + 8][ku + tig + 4];
            }
#pragma unroll
            for (int nt = 0; nt < 8; nt++) {
                int c = warpN * 64 + nt * 8 + gid;
                uint32_t b0 = Bs[cur][c][ku + tig];
                uint32_t b1 = Bs[cur][c][ku + tig + 4];
                MMA_BF16(acc[0][nt], af[0], b0, b1);
                MMA_BF16(acc[1][nt], af[1], b0, b1);
            }
        }
        if (t < 15) {
            const int nxt = cur ^ 1;
            *(uint4*)&As[nxt][row][hf*8]     = pa0;
            *(uint4*)&As[nxt][row][hf*8 + 4] = pa1;
            *(uint4*)&Bs[nxt][row][hf*8]     = pb0;
            *(uint4*)&Bs[nxt][row][hf*8 + 4] = pb1;
            __syncthreads();
        }
    }

#pragma unroll
    for (int mt = 0; mt < 2; mt++) {
#pragma unroll
        for (int nt = 0; nt < 8; nt++) {
            int r = m0 + warpM * 32 + mt * 16 + gid;
            int col = n0 + warpN * 64 + nt * 8 + 2 * tig;
            float2 v0 = make_float2(acc[mt][nt][0], acc[mt][nt][1]);
            float2 v1 = make_float2(acc[mt][nt][2], acc[mt][nt][3]);
            *(float2*)(g_logits + (size_t)r * V_ + col)       = v0;
            *(float2*)(g_logits + (size_t)(r + 8) * V_ + col) = v1;
        }
    }
}

// =====================  margin select + exact rescore (+hist)  =====================
__global__ __launch_bounds__(256, 4) void k_select() {
    __shared__ float s_red[8];
    __shared__ float s_bcast;
    __shared__ int   s_cnt;
    __shared__ int   s_cand[128];
    const int row = blockIdx.x;
    const int tid = threadIdx.x;
    const int wid = tid >> 5, lane = tid & 31;
    const float4* L = (const float4*)(g_logits + (size_t)row * V_);

    float4 v[4];
    float vmax = -1e30f;
#pragma unroll
    for (int j = 0; j < 4; j++) {
        v[j] = L[tid + j * 256];
        vmax = fmaxf(vmax, fmaxf(fmaxf(v[j].x, v[j].y), fmaxf(v[j].z, v[j].w)));
    }
#pragma unroll
    for (int o = 16; o; o >>= 1) vmax = fmaxf(vmax, __shfl_xor_sync(0xffffffffu, vmax, o));
    if (lane == 0) s_red[wid] = vmax;
    if (tid == 0) s_cnt = 0;
    __syncthreads();
    if (tid == 0) {
        float m = s_red[0];
#pragma unroll
        for (int i = 1; i < 8; i++) m = fmaxf(m, s_red[i]);
        s_bcast = m;
    }
    __syncthreads();
    const float kn = __int_as_float(g_knmax_i);
    const float margin = 0.02f * g_qnorm[row] * kn + 1e-6f;
    const float thr = s_bcast - margin;

#pragma unroll
    for (int j = 0; j < 4; j++) {
        int nb = (tid + j * 256) * 4;
        float a[4] = {v[j].x, v[j].y, v[j].z, v[j].w};
#pragma unroll
        for (int c = 0; c < 4; c++) {
            if (a[c] >= thr) {
                int p = atomicAdd(&s_cnt, 1);
                if (p < 128) s_cand[p] = nb + c;
            }
        }
    }
    __syncthreads();
    int cnt = min(s_cnt, 128);

    const float* qr = g_Q + (size_t)row * C_;
    float best_v = -1e30f;
    int best_n = 1 << 30;
    for (int c = 0; c < cnt; c++) {
        int n = s_cand[c];
        const float* kr = g_kh + (size_t)n * C_;
        float p = qr[2*tid] * kr[2*tid] + qr[2*tid+1] * kr[2*tid+1];
#pragma unroll
        for (int o = 16; o; o >>= 1) p += __shfl_xor_sync(0xffffffffu, p, o);
        if (lane == 0) s_red[wid] = p;
        __syncthreads();
        if (tid == 0) {
            float sum = 0.0f;
#pragma unroll
            for (int i = 0; i < 8; i++) sum += s_red[i];
            s_bcast = sum;
        }
        __syncthreads();
        float val = s_bcast;
        if (val > best_v || (val == best_v && n < best_n)) { best_v = val; best_n = n; }
        __syncthreads();
    }
    if (tid == 0) {
        g_idx[row] = best_n;
        if (row < MFULL) atomicAdd(&g_cnt[best_n], 1);
    }
}

// =====================  output kernels  =====================
__global__ void k_out(float* __restrict__ out) {
    int idx = blockIdx.x * blockDim.x + threadIdx.x;
    if (idx >= ZHAT_ELEMS) return;
    int t = idx & (T_ - 1);
    int d = (idx >> 10) & 511;
    int b = idx >> 19;
    float pos = (t + 0.5f) * ((float)Q_ / (float)T_) - 0.5f;
    pos = fminf(fmaxf(pos, 0.0f), (float)(Q_ - 1));
    int i0 = (int)pos;
    int i1 = min(i0 + 1, Q_ - 1);
    float w = pos - (float)i0;
    int n0 = g_idx[MFULL + b*Q_ + i0];
    int n1 = g_idx[MFULL + b*Q_ + i1];
    out[idx] = (1.0f - w) * g_value[(size_t)n0*C_ + d] + w * g_value[(size_t)n1*C_ + d];
}

__global__ void k_perp(float* __restrict__ out) {
    __shared__ float sm_[1024];
    int tid = threadIdx.x;
    float s = 0.0f;
    for (int j = tid; j < V_; j += 1024) {
        float p = (float)g_cnt[j] * (1.0f / 4096.0f);
        s += p * logf(p + 1e-7f);
    }
    sm_[tid] = s;
    __syncthreads();
    for (int o = 512; o; o >>= 1) {
        if (tid < o) sm_[tid] += sm_[tid + o];
        __syncthreads();
    }
    if (tid == 0) out[ZHAT_ELEMS] = expf(-sm_[0]);
}

// ---------------------------------------------------------------------------
extern "C" void kernel_launch(void* const* d_in, const int* in_sizes, int n_in,
                              void* d_out, int out_size) {
    const float* z        = (const float*)d_in[0];
    const float* codebook = (const float*)d_in[2];
    const float* Wq = (const float*)d_in[3];
    const float* bq = (const float*)d_in[4];
    const float* Wk = (const float*)d_in[5];
    const float* bk = (const float*)d_in[6];
    const float* Wv = (const float*)d_in[7];
    const float* bv = (const float*)d_in[8];
    const float* Wp = (const float*)d_in[9];
    const float* bp = (const float*)d_in[10];
    const float* gq = (const float*)d_in[11];
    const float* gk = (const float*)d_in[12];
    float* out = (float*)d_out;

    cudaFuncSetAttribute(k_proj_mma, cudaFuncAttributeMaxDynamicSharedMemorySize, PROJ_SMEM);

    k_transpose<<<dim3(16, 32, 4), dim3(32, 8)>>>(z);           // 1
    k_xp<<<16, 256>>>(Wp, bp);                                  // 2
    k_init<<<(V_ + 255)/256, 256>>>();                          // 3
    k_proj_mma<<<dim3(4, 32, 3), 256, PROJ_SMEM>>>(codebook, Wq, bq, Wk, bk, Wv, bv); // 4 (profiled)

    k_khnorm<<<V_,    512>>>(gk);
    k_qfull <<<MFULL, 512>>>(gq);
    k_qrest <<<MREST, 512>>>(gq);

    k_logits_mma<<<dim3(V_/128, MTOT/128), 256>>>();
    k_select<<<MTOT, 256>>>();

    k_out<<<(ZHAT_ELEMS + 255)/256, 256>>>(out);
    k_perp<<<1, 1024>>>(out);
}

// round 8
// speedup vs baseline: 1.0861x; 1.0861x over previous
#include <cuda_runtime.h>
#include <cuda_bf16.h>
#include <cstdint>

// Problem constants
#define B_    4
#define T_    1024
#define C_    512
#define V_    4096
#define H_    8
#define Q_    256
#define MFULL 4096
#define MREST 1024
#define MTOT  5120
#define ZHAT_ELEMS (B_*C_*T_)
#define COMB_SCALE 0.044194173824159216f

// ---- scratch ----
__device__ float g_hs[MFULL*C_];
__device__ float g_Xq[MFULL*C_];
__device__ float g_Xp[MFULL*H_];
__device__ float g_value[V_*C_];
__device__ float g_kh[V_*C_];
__device__ float g_Q[MTOT*C_];
__device__ __nv_bfloat16 g_Qh[MTOT*C_];
__device__ __nv_bfloat16 g_Kh[V_*C_];
__device__ __nv_bfloat16 g_logitsh[(size_t)MTOT*V_];   // 40MB bf16 approx logits (L2-resident)
__device__ float g_qnorm[MTOT];
__device__ int   g_knmax_i;
__device__ int   g_idx[MTOT];
__device__ int   g_cnt[V_];

// =====================  mma helpers  =====================
#define MMA_TF32(c, a, b0, b1) \
    asm volatile("mma.sync.aligned.m16n8k8.row.col.f32.tf32.tf32.f32 " \
        "{%0,%1,%2,%3}, {%4,%5,%6,%7}, {%8,%9}, {%0,%1,%2,%3};" \
        : "+f"((c)[0]), "+f"((c)[1]), "+f"((c)[2]), "+f"((c)[3]) \
        : "r"((a)[0]), "r"((a)[1]), "r"((a)[2]), "r"((a)[3]), "r"(b0), "r"(b1))

#define MMA_BF16(c, a, b0, b1) \
    asm volatile("mma.sync.aligned.m16n8k16.row.col.f32.bf16.bf16.f32 " \
        "{%0,%1,%2,%3}, {%4,%5,%6,%7}, {%8,%9}, {%0,%1,%2,%3};" \
        : "+f"((c)[0]), "+f"((c)[1]), "+f"((c)[2]), "+f"((c)[3]) \
        : "r"((a)[0]), "r"((a)[1]), "r"((a)[2]), "r"((a)[3]), "r"(b0), "r"(b1))

__device__ __forceinline__ uint32_t tf32_of(float x) {
    uint32_t r; asm("cvt.rna.tf32.f32 %0, %1;" : "=r"(r) : "f"(x)); return r;
}
#define SPLIT4(vh, vl, v) do { \
    (vh).x = tf32_of((v).x); (vl).x = tf32_of((v).x - __uint_as_float((vh).x)); \
    (vh).y = tf32_of((v).y); (vl).y = tf32_of((v).y - __uint_as_float((vh).y)); \
    (vh).z = tf32_of((v).z); (vl).z = tf32_of((v).z - __uint_as_float((vh).z)); \
    (vh).w = tf32_of((v).w); (vl).w = tf32_of((v).w - __uint_as_float((vh).w)); \
} while (0)

// =====================  small kernels  =====================
__global__ void k_init() {
    int i = blockIdx.x * blockDim.x + threadIdx.x;
    if (i < V_) g_cnt[i] = 0;
    if (i == 0) g_knmax_i = 0;
}

__global__ void k_transpose(const float* __restrict__ z) {
    __shared__ float tile[32][33];
    int b = blockIdx.z, c0 = blockIdx.x << 5, t0 = blockIdx.y << 5;
    int tx = threadIdx.x, ty = threadIdx.y;
#pragma unroll
    for (int j = 0; j < 4; j++)
        tile[ty + 8*j][tx] = z[(b*C_ + c0 + ty + 8*j)*T_ + t0 + tx];
    __syncthreads();
#pragma unroll
    for (int j = 0; j < 4; j++)
        g_hs[(b*T_ + t0 + ty + 8*j)*C_ + c0 + tx] = tile[tx][ty + 8*j];
}

__global__ __launch_bounds__(256) void k_xp(const float* __restrict__ Wp,
                                            const float* __restrict__ bp) {
    __shared__ float w[C_ * H_];
    int tid = threadIdx.x;
    for (int i = tid * 4; i < C_ * H_; i += 1024)
        *(float4*)&w[i] = *(const float4*)&Wp[i];
    __syncthreads();
    int row = blockIdx.x * 256 + tid;
    const float* hsr = g_hs + (size_t)row * C_;
    float acc[8];
#pragma unroll
    for (int j = 0; j < 8; j++) acc[j] = bp[j];
#pragma unroll 4
    for (int k = 0; k < C_; k += 4) {
        float4 hv = *(const float4*)(hsr + k);
        float h[4] = {hv.x, hv.y, hv.z, hv.w};
#pragma unroll
        for (int i = 0; i < 4; i++) {
            float4 wa = *(const float4*)&w[(k + i) * 8];
            float4 wb = *(const float4*)&w[(k + i) * 8 + 4];
            acc[0] += h[i] * wa.x; acc[1] += h[i] * wa.y;
            acc[2] += h[i] * wa.z; acc[3] += h[i] * wa.w;
            acc[4] += h[i] * wb.x; acc[5] += h[i] * wb.y;
            acc[6] += h[i] * wb.z; acc[7] += h[i] * wb.w;
        }
    }
    *(float4*)(g_Xp + row * 8)     = make_float4(acc[0], acc[1], acc[2], acc[3]);
    *(float4*)(g_Xp + row * 8 + 4) = make_float4(acc[4], acc[5], acc[6], acc[7]);
}

// =====================  split-tf32 projection GEMM (R6 layout)  =====================
#define PADA 20
#define PADB 136
#define AWRDS (128*PADA)
#define BWRDS (16*PADB)

__global__ __launch_bounds__(256, 2) void k_proj_mma(
    const float* __restrict__ cb,
    const float* __restrict__ Wq, const float* __restrict__ bq,
    const float* __restrict__ Wk, const float* __restrict__ bk,
    const float* __restrict__ Wv, const float* __restrict__ bv) {
    extern __shared__ __align__(16) unsigned char smraw[];
    uint32_t* AH = (uint32_t*)smraw;
    uint32_t* AL = AH + 2 * AWRDS;
    uint32_t* BH = AL + 2 * AWRDS;
    uint32_t* BL = BH + 2 * BWRDS;

    const float *A, *Bm, *bias; float* C;
    int zid = blockIdx.z;
    if (zid == 0)      { A = g_hs; Bm = Wq; bias = bq; C = g_Xq; }
    else if (zid == 1) { A = cb;   Bm = Wk; bias = bk; C = g_kh; }
    else               { A = cb;   Bm = Wv; bias = bv; C = g_value; }

    const int tid = threadIdx.x;
    const int wid = tid >> 5, lane = tid & 31;
    const int warpM = wid >> 1, warpN = wid & 1;
    const int m0 = blockIdx.y << 7, n0 = blockIdx.x << 7;
    const int ar = tid >> 2, ac = (tid & 3) << 2;
    const int br = tid >> 4, bc = (tid & 15) << 3;
    const int gid = lane >> 2, tig = lane & 3;

    const float* Ap = A  + (size_t)(m0 + ar) * C_ + ac;
    const float* Bp = Bm + (size_t)br * 512 + n0 + bc;

    {
        float4 va0 = *(const float4*)Ap;
        float4 va1 = *(const float4*)(Ap + 64 * C_);
        float4 vb0 = *(const float4*)Bp;
        float4 vb1 = *(const float4*)(Bp + 4);
        uint4 h, l;
        SPLIT4(h, l, va0); *(uint4*)&AH[ar*PADA + ac] = h; *(uint4*)&AL[ar*PADA + ac] = l;
        SPLIT4(h, l, va1); *(uint4*)&AH[(ar+64)*PADA + ac] = h; *(uint4*)&AL[(ar+64)*PADA + ac] = l;
        SPLIT4(h, l, vb0); *(uint4*)&BH[br*PADB + bc] = h; *(uint4*)&BL[br*PADB + bc] = l;
        SPLIT4(h, l, vb1); *(uint4*)&BH[br*PADB + bc + 4] = h; *(uint4*)&BL[br*PADB + bc + 4] = l;
    }
    __syncthreads();

    float acc[2][8][4] = {};
    for (int t = 0; t < 32; ++t) {
        const int cur = t & 1;
        const uint32_t ab = cur * AWRDS, bb = cur * BWRDS;
        float4 pa0, pa1, pb0, pb1;
        if (t < 31) {
            const float* A2 = Ap + (t + 1) * 16;
            const float* B2 = Bp + (size_t)(t + 1) * 16 * 512;
            pa0 = *(const float4*)A2;
            pa1 = *(const float4*)(A2 + 64 * C_);
            pb0 = *(const float4*)B2;
            pb1 = *(const float4*)(B2 + 4);
        }
#pragma unroll
        for (int ks = 0; ks < 16; ks += 8) {
            uint32_t ah[2][4], al[2][4];
#pragma unroll
            for (int mt = 0; mt < 2; mt++) {
                int r = warpM * 32 + mt * 16 + gid;
                ah[mt][0] = AH[ab + r*PADA + ks + tig];
                ah[mt][1] = AH[ab + (r+8)*PADA + ks + tig];
                ah[mt][2] = AH[ab + r*PADA + ks + tig + 4];
                ah[mt][3] = AH[ab + (r+8)*PADA + ks + tig + 4];
                al[mt][0] = AL[ab + r*PADA + ks + tig];
                al[mt][1] = AL[ab + (r+8)*PADA + ks + tig];
                al[mt][2] = AL[ab + r*PADA + ks + tig + 4];
                al[mt][3] = AL[ab + (r+8)*PADA + ks + tig + 4];
            }
#pragma unroll
            for (int nt = 0; nt < 8; nt++) {
                int c = warpN * 64 + nt * 8 + gid;
                uint32_t bh0 = BH[bb + (ks+tig)*PADB + c];
                uint32_t bh1 = BH[bb + (ks+tig+4)*PADB + c];
                uint32_t bl0 = BL[bb + (ks+tig)*PADB + c];
                uint32_t bl1 = BL[bb + (ks+tig+4)*PADB + c];
#pragma unroll
                for (int mt = 0; mt < 2; mt++) {
                    MMA_TF32(acc[mt][nt], ah[mt], bh0, bh1);
                    MMA_TF32(acc[mt][nt], ah[mt], bl0, bl1);
                    MMA_TF32(acc[mt][nt], al[mt], bh0, bh1);
                }
            }
        }
        if (t < 31) {
            const int nxt = cur ^ 1;
            const uint32_t ab2 = nxt * AWRDS, bb2 = nxt * BWRDS;
            uint4 h, l;
            SPLIT4(h, l, pa0); *(uint4*)&AH[ab2 + ar*PADA + ac] = h; *(uint4*)&AL[ab2 + ar*PADA + ac] = l;
            SPLIT4(h, l, pa1); *(uint4*)&AH[ab2 + (ar+64)*PADA + ac] = h; *(uint4*)&AL[ab2 + (ar+64)*PADA + ac] = l;
            SPLIT4(h, l, pb0); *(uint4*)&BH[bb2 + br*PADB + bc] = h; *(uint4*)&BL[bb2 + br*PADB + bc] = l;
            SPLIT4(h, l, pb1); *(uint4*)&BH[bb2 + br*PADB + bc + 4] = h; *(uint4*)&BL[bb2 + br*PADB + bc + 4] = l;
            __syncthreads();
        }
    }

#pragma unroll
    for (int mt = 0; mt < 2; mt++) {
#pragma unroll
        for (int nt = 0; nt < 8; nt++) {
            int row = m0 + warpM * 32 + mt * 16 + gid;
            int col = n0 + warpN * 64 + nt * 8 + 2 * tig;
            float b0 = bias[col], b1 = bias[col + 1];
            float2 v0 = make_float2(acc[mt][nt][0] + b0, acc[mt][nt][1] + b1);
            float2 v1 = make_float2(acc[mt][nt][2] + b0, acc[mt][nt][3] + b1);
            *(float2*)(C + (size_t)row * C_ + col)       = v0;
            *(float2*)(C + (size_t)(row + 8) * C_ + col) = v1;
        }
    }
}

// =====================  rmsnorm + combine kernels  =====================
__device__ __forceinline__ float head_rms_scale(float x, int d, float* ws) {
    float s = x * x;
#pragma unroll
    for (int o = 16; o; o >>= 1) s += __shfl_xor_sync(0xffffffffu, s, o);
    if ((d & 31) == 0) ws[d >> 5] = s;
    __syncthreads();
    int h = d >> 6;
    float tot = ws[2*h] + ws[2*h + 1];
    return rsqrtf(tot * (1.0f/64.0f) + 1e-5f);
}

__device__ __forceinline__ float block_sum_sq(float v, int d, float* s2) {
    float s = v * v;
#pragma unroll
    for (int o = 16; o; o >>= 1) s += __shfl_xor_sync(0xffffffffu, s, o);
    if ((d & 31) == 0) s2[d >> 5] = s;
    __syncthreads();
    float tot = 0.0f;
    if (d == 0) {
#pragma unroll
        for (int i = 0; i < 16; i++) tot += s2[i];
    }
    return tot;
}

__global__ void k_khnorm(const float* __restrict__ gk) {
    __shared__ float ws[16];
    __shared__ float s2[16];
    int row = blockIdx.x, d = threadIdx.x;
    float x = g_kh[(size_t)row*C_ + d];
    float r = head_rms_scale(x, d, ws);
    float v = x * r * gk[d & 63];
    g_kh[(size_t)row*C_ + d] = v;
    g_Kh[(size_t)row*C_ + d] = __float2bfloat16(v);
    __syncthreads();
    float n2 = block_sum_sq(v, d, s2);
    if (d == 0) atomicMax(&g_knmax_i, __float_as_int(sqrtf(n2)));
}

__global__ void k_qfull(const float* __restrict__ gq) {
    __shared__ float ws[16];
    __shared__ float s2[16];
    int row = blockIdx.x, d = threadIdx.x, h = d >> 6;
    float x = g_Xq[(size_t)row*C_ + d];
    float r = head_rms_scale(x, d, ws);
    float c = g_Xp[row*H_ + h];
    float v = x * r * gq[d & 63] * c * COMB_SCALE;
    g_Q[(size_t)row*C_ + d] = v;
    g_Qh[(size_t)row*C_ + d] = __float2bfloat16(v);
    __syncthreads();
    float n2 = block_sum_sq(v, d, s2);
    if (d == 0) g_qnorm[row] = sqrtf(n2);
}

__global__ void k_qrest(const float* __restrict__ gq) {
    __shared__ float ws[16];
    __shared__ float s2[16];
    int row = blockIdx.x, d = threadIdx.x, h = d >> 6;
    int fr = (row >> 8) * T_ + (row & 255) * 4;
    const float* p = g_Xq + (size_t)fr*C_ + d;
    float x = 0.25f * (p[0] + p[C_] + p[2*C_] + p[3*C_]);
    float r = head_rms_scale(x, d, ws);
    const float* pc = g_Xp + fr*H_ + h;
    float c = 0.25f * (pc[0] + pc[H_] + pc[2*H_] + pc[3*H_]);
    float v = x * r * gq[d & 63] * c * COMB_SCALE;
    g_Q[(size_t)(MFULL + row)*C_ + d] = v;
    g_Qh[(size_t)(MFULL + row)*C_ + d] = __float2bfloat16(v);
    __syncthreads();
    float n2 = block_sum_sq(v, d, s2);
    if (d == 0) g_qnorm[MFULL + row] = sqrtf(n2);
}

// =====================  bf16 mma.sync logits GEMM (NT), bf16 output  =====================
#define LPAD 20

__global__ __launch_bounds__(256, 2) void k_logits_mma() {
    __shared__ uint32_t As[2][128][LPAD];
    __shared__ uint32_t Bs[2][128][LPAD];
    const int tid = threadIdx.x;
    const int wid = tid >> 5, lane = tid & 31;
    const int warpM = wid >> 1, warpN = wid & 1;
    const int m0 = blockIdx.y << 7, n0 = blockIdx.x << 7;
    const int gid = lane >> 2, tig = lane & 3;
    const int row = tid >> 1, hf = tid & 1;

    const uint4* Ag = (const uint4*)(g_Qh + (size_t)(m0 + row) * C_) + hf * 2;
    const uint4* Bg = (const uint4*)(g_Kh + (size_t)(n0 + row) * C_) + hf * 2;

    {
        uint4 a0 = Ag[0], a1 = Ag[1];
        uint4 b0 = Bg[0], b1 = Bg[1];
        *(uint4*)&As[0][row][hf*8]     = a0;
        *(uint4*)&As[0][row][hf*8 + 4] = a1;
        *(uint4*)&Bs[0][row][hf*8]     = b0;
        *(uint4*)&Bs[0][row][hf*8 + 4] = b1;
    }
    __syncthreads();

    float acc[2][8][4] = {};
    for (int t = 0; t < 16; ++t) {
        const int cur = t & 1;
        uint4 pa0, pa1, pb0, pb1;
        if (t < 15) {
            const uint4* A2 = Ag + (t + 1) * 4;
            const uint4* B2 = Bg + (t + 1) * 4;
            pa0 = A2[0]; pa1 = A2[1];
            pb0 = B2[0]; pb1 = B2[1];
        }
#pragma unroll
        for (int ku = 0; ku < 16; ku += 8) {
            uint32_t af[2][4];
#pragma unroll
            for (int mt = 0; mt < 2; mt++) {
                int r = warpM * 32 + mt * 16 + gid;
                af[mt][0] = As[cur][r][ku + tig];
                af[mt][1] = As[cur][r + 8][ku + tig];
                af[mt][2] = As[cur][r][ku + tig + 4];
                af[mt][3] = As[cur][r + 8][ku + tig + 4];
            }
#pragma unroll
            for (int nt = 0; nt < 8; nt++) {
                int c = warpN * 64 + nt * 8 + gid;
                uint32_t b0 = Bs[cur][c][ku + tig];
                uint32_t b1 = Bs[cur][c][ku + tig + 4];
                MMA_BF16(acc[0][nt], af[0], b0, b1);
                MMA_BF16(acc[1][nt], af[1], b0, b1);
            }
        }
        if (t < 15) {
            const int nxt = cur ^ 1;
            *(uint4*)&As[nxt][row][hf*8]     = pa0;
            *(uint4*)&As[nxt][row][hf*8 + 4] = pa1;
            *(uint4*)&Bs[nxt][row][hf*8]     = pb0;
            *(uint4*)&Bs[nxt][row][hf*8 + 4] = pb1;
            __syncthreads();
        }
    }

#pragma unroll
    for (int mt = 0; mt < 2; mt++) {
#pragma unroll
        for (int nt = 0; nt < 8; nt++) {
            int r = m0 + warpM * 32 + mt * 16 + gid;
            int col = n0 + warpN * 64 + nt * 8 + 2 * tig;
            __nv_bfloat162 p0 = __floats2bfloat162_rn(acc[mt][nt][0], acc[mt][nt][1]);
            __nv_bfloat162 p1 = __floats2bfloat162_rn(acc[mt][nt][2], acc[mt][nt][3]);
            *(__nv_bfloat162*)(g_logitsh + (size_t)r * V_ + col)       = p0;
            *(__nv_bfloat162*)(g_logitsh + (size_t)(r + 8) * V_ + col) = p1;
        }
    }
}

// =====================  margin select + warp-parallel exact rescore (+hist)  =====================
// bound: mma 2^-7*qn*kn + bf16 storage 2^-9*qn*kn; margin = 2*bound*1.12 = 0.022
__global__ __launch_bounds__(256, 4) void k_select() {
    __shared__ float s_red[8];
    __shared__ float s_max;
    __shared__ int   s_cnt;
    __shared__ int   s_cand[128];
    __shared__ float s_cval[128];
    __shared__ float sq[C_];
    const int row = blockIdx.x;
    const int tid = threadIdx.x;
    const int wid = tid >> 5, lane = tid & 31;
    const uint4* L = (const uint4*)(g_logitsh + (size_t)row * V_);

    // stage q row into smem
    *(float2*)&sq[tid*2] = *(const float2*)(g_Q + (size_t)row * C_ + tid*2);

    uint4 u0 = L[tid], u1 = L[tid + 256];
    float vals[16];
    {
        uint32_t w[8] = {u0.x,u0.y,u0.z,u0.w, u1.x,u1.y,u1.z,u1.w};
#pragma unroll
        for (int q = 0; q < 8; q++) {
            float2 f = __bfloat1622float2(*(__nv_bfloat162*)&w[q]);
            vals[q*2] = f.x; vals[q*2+1] = f.y;
        }
    }
    float vmax = -1e30f;
#pragma unroll
    for (int q = 0; q < 16; q++) vmax = fmaxf(vmax, vals[q]);
#pragma unroll
    for (int o = 16; o; o >>= 1) vmax = fmaxf(vmax, __shfl_xor_sync(0xffffffffu, vmax, o));
    if (lane == 0) s_red[wid] = vmax;
    if (tid == 0) s_cnt = 0;
    __syncthreads();
    if (tid == 0) {
        float m = s_red[0];
#pragma unroll
        for (int i = 1; i < 8; i++) m = fmaxf(m, s_red[i]);
        s_max = m;
    }
    __syncthreads();
    const float kn = __int_as_float(g_knmax_i);
    const float margin = 0.022f * g_qnorm[row] * kn + 1e-6f;
    const float thr = s_max - margin;

#pragma unroll
    for (int q = 0; q < 16; q++) {
        if (vals[q] >= thr) {
            int base = (q < 8) ? (tid * 8 + q) : (2048 + tid * 8 + (q - 8));
            int p = atomicAdd(&s_cnt, 1);
            if (p < 128) s_cand[p] = base;
        }
    }
    __syncthreads();
    int cnt = min(s_cnt, 128);

    // warp-parallel exact rescore: warp w handles candidates w, w+8, ...
    for (int c = wid; c < cnt; c += 8) {
        int n = s_cand[c];
        const float* kr = g_kh + (size_t)n * C_;
        float p = 0.0f;
#pragma unroll
        for (int i = 0; i < 16; i++) p += sq[i*32 + lane] * kr[i*32 + lane];
#pragma unroll
        for (int o = 16; o; o >>= 1) p += __shfl_xor_sync(0xffffffffu, p, o);
        if (lane == 0) s_cval[c] = p;
    }
    __syncthreads();
    if (tid == 0) {
        float best_v = -1e30f;
        int best_n = 1 << 30;
        for (int c = 0; c < cnt; c++) {
            float v = s_cval[c];
            int n = s_cand[c];
            if (v > best_v || (v == best_v && n < best_n)) { best_v = v; best_n = n; }
        }
        g_idx[row] = best_n;
        if (row < MFULL) atomicAdd(&g_cnt[best_n], 1);
    }
}

// =====================  output kernels  =====================
__global__ void k_out(float* __restrict__ out) {
    int idx = blockIdx.x * blockDim.x + threadIdx.x;
    if (idx >= ZHAT_ELEMS) return;
    int t = idx & (T_ - 1);
    int d = (idx >> 10) & 511;
    int b = idx >> 19;
    float pos = (t + 0.5f) * ((float)Q_ / (float)T_) - 0.5f;
    pos = fminf(fmaxf(pos, 0.0f), (float)(Q_ - 1));
    int i0 = (int)pos;
    int i1 = min(i0 + 1, Q_ - 1);
    float w = pos - (float)i0;
    int n0 = g_idx[MFULL + b*Q_ + i0];
    int n1 = g_idx[MFULL + b*Q_ + i1];
    out[idx] = (1.0f - w) * g_value[(size_t)n0*C_ + d] + w * g_value[(size_t)n1*C_ + d];
}

__global__ void k_perp(float* __restrict__ out) {
    __shared__ float sm_[1024];
    int tid = threadIdx.x;
    float s = 0.0f;
    for (int j = tid; j < V_; j += 1024) {
        float p = (float)g_cnt[j] * (1.0f / 4096.0f);
        s += p * logf(p + 1e-7f);
    }
    sm_[tid] = s;
    __syncthreads();
    for (int o = 512; o; o >>= 1) {
        if (tid < o) sm_[tid] += sm_[tid + o];
        __syncthreads();
    }
    if (tid == 0) out[ZHAT_ELEMS] = expf(-sm_[0]);
}

// ---------------------------------------------------------------------------
extern "C" void kernel_launch(void* const* d_in, const int* in_sizes, int n_in,
                              void* d_out, int out_size) {
    const float* z        = (const float*)d_in[0];
    const float* codebook = (const float*)d_in[2];
    const float* Wq = (const float*)d_in[3];
    const float* bq = (const float*)d_in[4];
    const float* Wk = (const float*)d_in[5];
    const float* bk = (const float*)d_in[6];
    const float* Wv = (const float*)d_in[7];
    const float* bv = (const float*)d_in[8];
    const float* Wp = (const float*)d_in[9];
    const float* bp = (const float*)d_in[10];
    const float* gq = (const float*)d_in[11];
    const float* gk = (const float*)d_in[12];
    float* out = (float*)d_out;

    const int proj_smem = (4*AWRDS + 4*BWRDS) * 4;
    cudaFuncSetAttribute(k_proj_mma, cudaFuncAttributeMaxDynamicSharedMemorySize, proj_smem);

    k_transpose<<<dim3(16, 32, 4), dim3(32, 8)>>>(z);           // 1
    k_xp<<<16, 256>>>(Wp, bp);                                  // 2
    k_init<<<(V_ + 255)/256, 256>>>();                          // 3
    k_proj_mma<<<dim3(4, 32, 3), 256, proj_smem>>>(codebook, Wq, bq, Wk, bk, Wv, bv); // 4 (profiled)

    k_khnorm<<<V_,    512>>>(gk);
    k_qfull <<<MFULL, 512>>>(gq);
    k_qrest <<<MREST, 512>>>(gq);

    k_logits_mma<<<dim3(V_/128, MTOT/128), 256>>>();
    k_select<<<MTOT, 256>>>();

    k_out<<<(ZHAT_ELEMS + 255)/256, 256>>>(out);
    k_perp<<<1, 1024>>>(out);
}

// round 10
// speedup vs baseline: 1.1561x; 1.0644x over previous
#include <cuda_runtime.h>
#include <cuda_bf16.h>
#include <cstdint>

// Problem constants
#define B_    4
#define T_    1024
#define C_    512
#define V_    4096
#define H_    8
#define Q_    256
#define MFULL 4096
#define MREST 1024
#define MTOT  5120
#define ZHAT_ELEMS (B_*C_*T_)
#define COMB_SCALE 0.044194173824159216f

// ---- scratch ----
__device__ float g_hs[MFULL*C_];
__device__ float g_Xq[MFULL*C_];
__device__ float g_Xp[MFULL*H_];
__device__ float g_value[V_*C_];
__device__ float g_kh[V_*C_];
__device__ float g_Q[MTOT*C_];
__device__ __nv_bfloat16 g_Qh[MTOT*C_];
__device__ __nv_bfloat16 g_Kh[V_*C_];
__device__ __nv_bfloat16 g_logitsh[(size_t)MTOT*V_];
__device__ float g_qnorm[MTOT];
__device__ int   g_knmax_i;
__device__ int   g_idx[MTOT];
__device__ int   g_cnt[V_];

// =====================  mma / cp.async helpers  =====================
#define MMA_TF32(c, a, b0, b1) \
    asm volatile("mma.sync.aligned.m16n8k8.row.col.f32.tf32.tf32.f32 " \
        "{%0,%1,%2,%3}, {%4,%5,%6,%7}, {%8,%9}, {%0,%1,%2,%3};" \
        : "+f"((c)[0]), "+f"((c)[1]), "+f"((c)[2]), "+f"((c)[3]) \
        : "r"((a)[0]), "r"((a)[1]), "r"((a)[2]), "r"((a)[3]), "r"(b0), "r"(b1))

#define MMA_BF16(c, a, b0, b1) \
    asm volatile("mma.sync.aligned.m16n8k16.row.col.f32.bf16.bf16.f32 " \
        "{%0,%1,%2,%3}, {%4,%5,%6,%7}, {%8,%9}, {%0,%1,%2,%3};" \
        : "+f"((c)[0]), "+f"((c)[1]), "+f"((c)[2]), "+f"((c)[3]) \
        : "r"((a)[0]), "r"((a)[1]), "r"((a)[2]), "r"((a)[3]), "r"(b0), "r"(b1))

__device__ __forceinline__ void cp16(uint32_t dst, const void* src) {
    asm volatile("cp.async.cg.shared.global [%0], [%1], 16;" :: "r"(dst), "l"(src));
}
#define CP_COMMIT() asm volatile("cp.async.commit_group;" ::: "memory")
#define CP_WAIT1()  asm volatile("cp.async.wait_group 1;" ::: "memory")
#define CP_WAIT0()  asm volatile("cp.async.wait_group 0;" ::: "memory")

__device__ __forceinline__ uint32_t tf32_of(float x) {
    uint32_t r; asm("cvt.rna.tf32.f32 %0, %1;" : "=r"(r) : "f"(x)); return r;
}
__device__ __forceinline__ void split1(float x, uint32_t& h, uint32_t& l) {
    h = tf32_of(x);
    l = tf32_of(x - __uint_as_float(h));
}

// =====================  small kernels  =====================
__global__ void k_init() {
    int i = blockIdx.x * blockDim.x + threadIdx.x;
    if (i < V_) g_cnt[i] = 0;
    if (i == 0) g_knmax_i = 0;
}

__global__ void k_transpose(const float* __restrict__ z) {
    __shared__ float tile[32][33];
    int b = blockIdx.z, c0 = blockIdx.x << 5, t0 = blockIdx.y << 5;
    int tx = threadIdx.x, ty = threadIdx.y;
#pragma unroll
    for (int j = 0; j < 4; j++)
        tile[ty + 8*j][tx] = z[(b*C_ + c0 + ty + 8*j)*T_ + t0 + tx];
    __syncthreads();
#pragma unroll
    for (int j = 0; j < 4; j++)
        g_hs[(b*T_ + t0 + ty + 8*j)*C_ + c0 + tx] = tile[tx][ty + 8*j];
}

__global__ __launch_bounds__(256) void k_xp(const float* __restrict__ Wp,
                                            const float* __restrict__ bp) {
    __shared__ float w[C_ * H_];
    int tid = threadIdx.x;
    for (int i = tid * 4; i < C_ * H_; i += 1024)
        *(float4*)&w[i] = *(const float4*)&Wp[i];
    __syncthreads();
    int row = blockIdx.x * 256 + tid;
    const float* hsr = g_hs + (size_t)row * C_;
    float acc[8];
#pragma unroll
    for (int j = 0; j < 8; j++) acc[j] = bp[j];
#pragma unroll 4
    for (int k = 0; k < C_; k += 4) {
        float4 hv = *(const float4*)(hsr + k);
        float h[4] = {hv.x, hv.y, hv.z, hv.w};
#pragma unroll
        for (int i = 0; i < 4; i++) {
            float4 wa = *(const float4*)&w[(k + i) * 8];
            float4 wb = *(const float4*)&w[(k + i) * 8 + 4];
            acc[0] += h[i] * wa.x; acc[1] += h[i] * wa.y;
            acc[2] += h[i] * wa.z; acc[3] += h[i] * wa.w;
            acc[4] += h[i] * wb.x; acc[5] += h[i] * wb.y;
            acc[6] += h[i] * wb.z; acc[7] += h[i] * wb.w;
        }
    }
    *(float4*)(g_Xp + row * 8)     = make_float4(acc[0], acc[1], acc[2], acc[3]);
    *(float4*)(g_Xp + row * 8 + 4) = make_float4(acc[4], acc[5], acc[6], acc[7]);
}

// =====================  split-tf32 projection GEMM, cp.async 3-stage, raw smem  =====================
// A stage: 128 rows x (16 k-words + 4 pad) = 2560 words.  B stage: 16 k-rows x 136 = 2176 words.
#define PAW 2560
#define PBW 2176
#define PROJ_SMEM ((3*PAW + 3*PBW) * 4)   // 56832 B

__global__ __launch_bounds__(256, 2) void k_proj_mma(
    const float* __restrict__ cb,
    const float* __restrict__ Wq, const float* __restrict__ bq,
    const float* __restrict__ Wk, const float* __restrict__ bk,
    const float* __restrict__ Wv, const float* __restrict__ bv) {
    extern __shared__ __align__(16) unsigned char smraw[];
    const uint32_t smb = (uint32_t)__cvta_generic_to_shared(smraw);

    const float *A, *Bm, *bias; float* C;
    int zid = blockIdx.z;
    if (zid == 0)      { A = g_hs; Bm = Wq; bias = bq; C = g_Xq; }
    else if (zid == 1) { A = cb;   Bm = Wk; bias = bk; C = g_kh; }
    else               { A = cb;   Bm = Wv; bias = bv; C = g_value; }

    const int tid = threadIdx.x;
    const int wid = tid >> 5, lane = tid & 31;
    const int warpM = wid >> 1, warpN = wid & 1;
    const int m0 = blockIdx.y << 7, n0 = blockIdx.x << 7;
    const int ar = tid >> 2, ac = (tid & 3) << 2;
    const int br = tid >> 4, bc = (tid & 15) << 3;
    const int gid = lane >> 2, tig = lane & 3;

    const float* Ag = A + (size_t)(m0 + ar) * C_ + ac;      // + t*16

    const uint32_t dA0 = (uint32_t)(ar * 20 + ac) * 4;
    const uint32_t dA1 = (uint32_t)((ar + 64) * 20 + ac) * 4;
    const uint32_t dB0 = (uint32_t)(br * 136 + bc) * 4;
    const uint32_t dB1 = dB0 + 16;

#define PROJ_ISSUE(s) do { \
    const int _b = (s) % 3; \
    const uint32_t _ab = smb + (uint32_t)_b * (PAW * 4); \
    const uint32_t _bb = smb + (uint32_t)(3 * PAW + _b * PBW) * 4; \
    const float* _A = Ag + (s) * 16; \
    const float* _B = Bm + (size_t)((s) * 16 + br) * 512 + n0 + bc; \
    cp16(_ab + dA0, _A); \
    cp16(_ab + dA1, _A + 64 * C_); \
    cp16(_bb + dB0, _B); \
    cp16(_bb + dB1, _B + 4); \
    CP_COMMIT(); \
} while (0)

    PROJ_ISSUE(0);
    PROJ_ISSUE(1);

    float acc[2][8][4] = {};
    for (int t = 0; t < 32; ++t) {
        const int buf = t % 3;
        if (t + 1 < 32) CP_WAIT1(); else CP_WAIT0();
        __syncthreads();
        if (t + 2 < 32) PROJ_ISSUE(t + 2);

        const float* ASf = (const float*)smraw + buf * PAW;
        const float* BSf = (const float*)smraw + 3 * PAW + buf * PBW;
#pragma unroll
        for (int ks8 = 0; ks8 < 2; ks8++) {
            const int kb = ks8 * 8 + tig;
            uint32_t ah[2][4], al[2][4];
#pragma unroll
            for (int mt = 0; mt < 2; mt++) {
                int r = warpM * 32 + mt * 16 + gid;
                float x0 = ASf[r * 20 + kb];
                float x1 = ASf[(r + 8) * 20 + kb];
                float x2 = ASf[r * 20 + kb + 4];
                float x3 = ASf[(r + 8) * 20 + kb + 4];
                split1(x0, ah[mt][0], al[mt][0]);
                split1(x1, ah[mt][1], al[mt][1]);
                split1(x2, ah[mt][2], al[mt][2]);
                split1(x3, ah[mt][3], al[mt][3]);
            }
#pragma unroll
            for (int nt = 0; nt < 8; nt++) {
                int c = warpN * 64 + nt * 8 + gid;
                float y0 = BSf[kb * 136 + c];
                float y1 = BSf[(kb + 4) * 136 + c];
                uint32_t bh0, bl0, bh1, bl1;
                split1(y0, bh0, bl0);
                split1(y1, bh1, bl1);
#pragma unroll
                for (int mt = 0; mt < 2; mt++) {
                    MMA_TF32(acc[mt][nt], ah[mt], bh0, bh1);
                    MMA_TF32(acc[mt][nt], ah[mt], bl0, bl1);
                    MMA_TF32(acc[mt][nt], al[mt], bh0, bh1);
                }
            }
        }
        __syncthreads();
    }

#pragma unroll
    for (int mt = 0; mt < 2; mt++) {
#pragma unroll
        for (int nt = 0; nt < 8; nt++) {
            int row = m0 + warpM * 32 + mt * 16 + gid;
            int col = n0 + warpN * 64 + nt * 8 + 2 * tig;
            float b0 = bias[col], b1 = bias[col + 1];
            float2 v0 = make_float2(acc[mt][nt][0] + b0, acc[mt][nt][1] + b1);
            float2 v1 = make_float2(acc[mt][nt][2] + b0, acc[mt][nt][3] + b1);
            *(float2*)(C + (size_t)row * C_ + col)       = v0;
            *(float2*)(C + (size_t)(row + 8) * C_ + col) = v1;
        }
    }
#undef PROJ_ISSUE
}

// =====================  rmsnorm + combine kernels  =====================
__device__ __forceinline__ float head_rms_scale(float x, int d, float* ws) {
    float s = x * x;
#pragma unroll
    for (int o = 16; o; o >>= 1) s += __shfl_xor_sync(0xffffffffu, s, o);
    if ((d & 31) == 0) ws[d >> 5] = s;
    __syncthreads();
    int h = d >> 6;
    float tot = ws[2*h] + ws[2*h + 1];
    return rsqrtf(tot * (1.0f/64.0f) + 1e-5f);
}

__device__ __forceinline__ float block_sum_sq(float v, int d, float* s2) {
    float s = v * v;
#pragma unroll
    for (int o = 16; o; o >>= 1) s += __shfl_xor_sync(0xffffffffu, s, o);
    if ((d & 31) == 0) s2[d >> 5] = s;
    __syncthreads();
    float tot = 0.0f;
    if (d == 0) {
#pragma unroll
        for (int i = 0; i < 16; i++) tot += s2[i];
    }
    return tot;
}

__global__ void k_khnorm(const float* __restrict__ gk) {
    __shared__ float ws[16];
    __shared__ float s2[16];
    int row = blockIdx.x, d = threadIdx.x;
    float x = g_kh[(size_t)row*C_ + d];
    float r = head_rms_scale(x, d, ws);
    float v = x * r * gk[d & 63];
    g_kh[(size_t)row*C_ + d] = v;
    g_Kh[(size_t)row*C_ + d] = __float2bfloat16(v);
    __syncthreads();
    float n2 = block_sum_sq(v, d, s2);
    if (d == 0) atomicMax(&g_knmax_i, __float_as_int(sqrtf(n2)));
}

__global__ void k_qfull(const float* __restrict__ gq) {
    __shared__ float ws[16];
    __shared__ float s2[16];
    int row = blockIdx.x, d = threadIdx.x, h = d >> 6;
    float x = g_Xq[(size_t)row*C_ + d];
    float r = head_rms_scale(x, d, ws);
    float c = g_Xp[row*H_ + h];
    float v = x * r * gq[d & 63] * c * COMB_SCALE;
    g_Q[(size_t)row*C_ + d] = v;
    g_Qh[(size_t)row*C_ + d] = __float2bfloat16(v);
    __syncthreads();
    float n2 = block_sum_sq(v, d, s2);
    if (d == 0) g_qnorm[row] = sqrtf(n2);
}

__global__ void k_qrest(const float* __restrict__ gq) {
    __shared__ float ws[16];
    __shared__ float s2[16];
    int row = blockIdx.x, d = threadIdx.x, h = d >> 6;
    int fr = (row >> 8) * T_ + (row & 255) * 4;
    const float* p = g_Xq + (size_t)fr*C_ + d;
    float x = 0.25f * (p[0] + p[C_] + p[2*C_] + p[3*C_]);
    float r = head_rms_scale(x, d, ws);
    const float* pc = g_Xp + fr*H_ + h;
    float c = 0.25f * (pc[0] + pc[H_] + pc[2*H_] + pc[3*H_]);
    float v = x * r * gq[d & 63] * c * COMB_SCALE;
    g_Q[(size_t)(MFULL + row)*C_ + d] = v;
    g_Qh[(size_t)(MFULL + row)*C_ + d] = __float2bfloat16(v);
    __syncthreads();
    float n2 = block_sum_sq(v, d, s2);
    if (d == 0) g_qnorm[MFULL + row] = sqrtf(n2);
}

// =====================  bf16 logits GEMM, cp.async 3-stage  =====================
// tile stage: 128 rows x (16 uints + 4 pad) = 2560 words (32 halves per row-chunk)
#define LAW 2560
#define LOG_SMEM ((6 * LAW) * 4)   // 61440 B

__global__ __launch_bounds__(256, 2) void k_logits_mma() {
    extern __shared__ __align__(16) unsigned char smraw[];
    const uint32_t smb = (uint32_t)__cvta_generic_to_shared(smraw);
    const int tid = threadIdx.x;
    const int wid = tid >> 5, lane = tid & 31;
    const int warpM = wid >> 1, warpN = wid & 1;
    const int m0 = blockIdx.y << 7, n0 = blockIdx.x << 7;
    const int gid = lane >> 2, tig = lane & 3;
    const int row = tid >> 1, hf = tid & 1;

    const char* Ag = (const char*)(g_Qh + (size_t)(m0 + row) * C_) + hf * 32;  // + t*64
    const char* Bg = (const char*)(g_Kh + (size_t)(n0 + row) * C_) + hf * 32;
    const uint32_t dT = (uint32_t)(row * 20 + hf * 8) * 4;   // hf segment = 8 words = 32 B

// FIX (R9 bug): each hf segment is 32 bytes -> TWO cp16 per operand per stage.
#define LOG_ISSUE(s) do { \
    const int _b = (s) % 3; \
    const uint32_t _a = smb + (uint32_t)(_b * LAW) * 4 + dT; \
    const uint32_t _bb = smb + (uint32_t)((3 + _b) * LAW) * 4 + dT; \
    cp16(_a,       Ag + (s) * 64); \
    cp16(_a + 16,  Ag + (s) * 64 + 16); \
    cp16(_bb,      Bg + (s) * 64); \
    cp16(_bb + 16, Bg + (s) * 64 + 16); \
    CP_COMMIT(); \
} while (0)

    LOG_ISSUE(0);
    LOG_ISSUE(1);

    float acc[2][8][4] = {};
    for (int t = 0; t < 16; ++t) {
        const int buf = t % 3;
        if (t + 1 < 16) CP_WAIT1(); else CP_WAIT0();
        __syncthreads();
        if (t + 2 < 16) LOG_ISSUE(t + 2);

        const uint32_t* As = (const uint32_t*)smraw + buf * LAW;
        const uint32_t* Bs = (const uint32_t*)smraw + (3 + buf) * LAW;
#pragma unroll
        for (int ku = 0; ku < 16; ku += 8) {
            uint32_t af[2][4];
#pragma unroll
            for (int mt = 0; mt < 2; mt++) {
                int r = warpM * 32 + mt * 16 + gid;
                af[mt][0] = As[r * 20 + ku + tig];
                af[mt][1] = As[(r + 8) * 20 + ku + tig];
                af[mt][2] = As[r * 20 + ku + tig + 4];
                af[mt][3] = As[(r + 8) * 20 + ku + tig + 4];
            }
#pragma unroll
            for (int nt = 0; nt < 8; nt++) {
                int c = warpN * 64 + nt * 8 + gid;
                uint32_t b0 = Bs[c * 20 + ku + tig];
                uint32_t b1 = Bs[c * 20 + ku + tig + 4];
                MMA_BF16(acc[0][nt], af[0], b0, b1);
                MMA_BF16(acc[1][nt], af[1], b0, b1);
            }
        }
        __syncthreads();
    }

#pragma unroll
    for (int mt = 0; mt < 2; mt++) {
#pragma unroll
        for (int nt = 0; nt < 8; nt++) {
            int r = m0 + warpM * 32 + mt * 16 + gid;
            int col = n0 + warpN * 64 + nt * 8 + 2 * tig;
            __nv_bfloat162 p0 = __floats2bfloat162_rn(acc[mt][nt][0], acc[mt][nt][1]);
            __nv_bfloat162 p1 = __floats2bfloat162_rn(acc[mt][nt][2], acc[mt][nt][3]);
            *(__nv_bfloat162*)(g_logitsh + (size_t)r * V_ + col)       = p0;
            *(__nv_bfloat162*)(g_logitsh + (size_t)(r + 8) * V_ + col) = p1;
        }
    }
#undef LOG_ISSUE
}

// =====================  margin select + warp-parallel exact rescore (+hist)  =====================
__global__ __launch_bounds__(256, 4) void k_select() {
    __shared__ float s_red[8];
    __shared__ float s_max;
    __shared__ int   s_cnt;
    __shared__ int   s_cand[128];
    __shared__ float s_cval[128];
    __shared__ float sq[C_];
    const int row = blockIdx.x;
    const int tid = threadIdx.x;
    const int wid = tid >> 5, lane = tid & 31;
    const uint4* L = (const uint4*)(g_logitsh + (size_t)row * V_);

    *(float2*)&sq[tid*2] = *(const float2*)(g_Q + (size_t)row * C_ + tid*2);

    uint4 u0 = L[tid], u1 = L[tid + 256];
    float vals[16];
    {
        uint32_t w[8] = {u0.x,u0.y,u0.z,u0.w, u1.x,u1.y,u1.z,u1.w};
#pragma unroll
        for (int q = 0; q < 8; q++) {
            float2 f = __bfloat1622float2(*(__nv_bfloat162*)&w[q]);
            vals[q*2] = f.x; vals[q*2+1] = f.y;
        }
    }
    float vmax = -1e30f;
#pragma unroll
    for (int q = 0; q < 16; q++) vmax = fmaxf(vmax, vals[q]);
#pragma unroll
    for (int o = 16; o; o >>= 1) vmax = fmaxf(vmax, __shfl_xor_sync(0xffffffffu, vmax, o));
    if (lane == 0) s_red[wid] = vmax;
    if (tid == 0) s_cnt = 0;
    __syncthreads();
    if (tid == 0) {
        float m = s_red[0];
#pragma unroll
        for (int i = 1; i < 8; i++) m = fmaxf(m, s_red[i]);
        s_max = m;
    }
    __syncthreads();
    const float kn = __int_as_float(g_knmax_i);
    const float margin = 0.022f * g_qnorm[row] * kn + 1e-6f;
    const float thr = s_max - margin;

#pragma unroll
    for (int q = 0; q < 16; q++) {
        if (vals[q] >= thr) {
            int base = (q < 8) ? (tid * 8 + q) : (2048 + tid * 8 + (q - 8));
            int p = atomicAdd(&s_cnt, 1);
            if (p < 128) s_cand[p] = base;
        }
    }
    __syncthreads();
    int cnt = min(s_cnt, 128);

    for (int c = wid; c < cnt; c += 8) {
        int n = s_cand[c];
        const float* kr = g_kh + (size_t)n * C_;
        float p = 0.0f;
#pragma unroll
        for (int i = 0; i < 16; i++) p += sq[i*32 + lane] * kr[i*32 + lane];
#pragma unroll
        for (int o = 16; o; o >>= 1) p += __shfl_xor_sync(0xffffffffu, p, o);
        if (lane == 0) s_cval[c] = p;
    }
    __syncthreads();
    if (tid == 0) {
        float best_v = -1e30f;
        int best_n = 1 << 30;
        for (int c = 0; c < cnt; c++) {
            float v = s_cval[c];
            int n = s_cand[c];
            if (v > best_v || (v == best_v && n < best_n)) { best_v = v; best_n = n; }
        }
        g_idx[row] = best_n;
        if (row < MFULL) atomicAdd(&g_cnt[best_n], 1);
    }
}

// =====================  output kernels  =====================
__global__ void k_out(float* __restrict__ out) {
    int idx = blockIdx.x * blockDim.x + threadIdx.x;
    if (idx >= ZHAT_ELEMS) return;
    int t = idx & (T_ - 1);
    int d = (idx >> 10) & 511;
    int b = idx >> 19;
    float pos = (t + 0.5f) * ((float)Q_ / (float)T_) - 0.5f;
    pos = fminf(fmaxf(pos, 0.0f), (float)(Q_ - 1));
    int i0 = (int)pos;
    int i1 = min(i0 + 1, Q_ - 1);
    float w = pos - (float)i0;
    int n0 = g_idx[MFULL + b*Q_ + i0];
    int n1 = g_idx[MFULL + b*Q_ + i1];
    out[idx] = (1.0f - w) * g_value[(size_t)n0*C_ + d] + w * g_value[(size_t)n1*C_ + d];
}

__global__ void k_perp(float* __restrict__ out) {
    __shared__ float sm_[1024];
    int tid = threadIdx.x;
    float s = 0.0f;
    for (int j = tid; j < V_; j += 1024) {
        float p = (float)g_cnt[j] * (1.0f / 4096.0f);
        s += p * logf(p + 1e-7f);
    }
    sm_[tid] = s;
    __syncthreads();
    for (int o = 512; o; o >>= 1) {
        if (tid < o) sm_[tid] += sm_[tid + o];
        __syncthreads();
    }
    if (tid == 0) out[ZHAT_ELEMS] = expf(-sm_[0]);
}

// ---------------------------------------------------------------------------
extern "C" void kernel_launch(void* const* d_in, const int* in_sizes, int n_in,
                              void* d_out, int out_size) {
    const float* z        = (const float*)d_in[0];
    const float* codebook = (const float*)d_in[2];
    const float* Wq = (const float*)d_in[3];
    const float* bq = (const float*)d_in[4];
    const float* Wk = (const float*)d_in[5];
    const float* bk = (const float*)d_in[6];
    const float* Wv = (const float*)d_in[7];
    const float* bv = (const float*)d_in[8];
    const float* Wp = (const float*)d_in[9];
    const float* bp = (const float*)d_in[10];
    const float* gq = (const float*)d_in[11];
    const float* gk = (const float*)d_in[12];
    float* out = (float*)d_out;

    cudaFuncSetAttribute(k_proj_mma, cudaFuncAttributeMaxDynamicSharedMemorySize, PROJ_SMEM);
    cudaFuncSetAttribute(k_logits_mma, cudaFuncAttributeMaxDynamicSharedMemorySize, LOG_SMEM);

    k_transpose<<<dim3(16, 32, 4), dim3(32, 8)>>>(z);           // 1
    k_xp<<<16, 256>>>(Wp, bp);                                  // 2
    k_init<<<(V_ + 255)/256, 256>>>();                          // 3
    k_proj_mma<<<dim3(4, 32, 3), 256, PROJ_SMEM>>>(codebook, Wq, bq, Wk, bk, Wv, bv); // 4 (profiled)

    k_khnorm<<<V_,    512>>>(gk);
    k_qfull <<<MFULL, 512>>>(gq);
    k_qrest <<<MREST, 512>>>(gq);

    k_logits_mma<<<dim3(V_/128, MTOT/128), 256, LOG_SMEM>>>();
    k_select<<<MTOT, 256>>>();

    k_out<<<(ZHAT_ELEMS + 255)/256, 256>>>(out);
    k_perp<<<1, 1024>>>(out);
}

// round 11
// speedup vs baseline: 1.1635x; 1.0065x over previous
#include <cuda_runtime.h>
#include <cuda_bf16.h>
#include <cstdint>

// Problem constants
#define B_    4
#define T_    1024
#define C_    512
#define V_    4096
#define H_    8
#define Q_    256
#define MFULL 4096
#define MREST 1024
#define MTOT  5120
#define ZHAT_ELEMS (B_*C_*T_)
#define COMB_SCALE 0.044194173824159216f

// ---- scratch ----
__device__ float g_hs[MFULL*C_];
__device__ float g_Xq[MFULL*C_];
__device__ float g_Xp[MFULL*H_];
__device__ float g_value[V_*C_];
__device__ float g_kh[V_*C_];
__device__ float g_Q[MTOT*C_];
__device__ __nv_bfloat16 g_Qh[MTOT*C_];
__device__ __nv_bfloat16 g_Kh[V_*C_];
__device__ __nv_bfloat16 g_logitsh[(size_t)MTOT*V_];
__device__ float g_qnorm[MTOT];
__device__ int   g_knmax_i;
__device__ int   g_idx[MTOT];
__device__ int   g_cnt[V_];

// =====================  mma / cp.async helpers  =====================
#define MMA_TF32(c, a, b0, b1) \
    asm volatile("mma.sync.aligned.m16n8k8.row.col.f32.tf32.tf32.f32 " \
        "{%0,%1,%2,%3}, {%4,%5,%6,%7}, {%8,%9}, {%0,%1,%2,%3};" \
        : "+f"((c)[0]), "+f"((c)[1]), "+f"((c)[2]), "+f"((c)[3]) \
        : "r"((a)[0]), "r"((a)[1]), "r"((a)[2]), "r"((a)[3]), "r"(b0), "r"(b1))

#define MMA_BF16(c, a, b0, b1) \
    asm volatile("mma.sync.aligned.m16n8k16.row.col.f32.bf16.bf16.f32 " \
        "{%0,%1,%2,%3}, {%4,%5,%6,%7}, {%8,%9}, {%0,%1,%2,%3};" \
        : "+f"((c)[0]), "+f"((c)[1]), "+f"((c)[2]), "+f"((c)[3]) \
        : "r"((a)[0]), "r"((a)[1]), "r"((a)[2]), "r"((a)[3]), "r"(b0), "r"(b1))

__device__ __forceinline__ void cp16(uint32_t dst, const void* src) {
    asm volatile("cp.async.cg.shared.global [%0], [%1], 16;" :: "r"(dst), "l"(src));
}
#define CP_COMMIT() asm volatile("cp.async.commit_group;" ::: "memory")
#define CP_WAIT1()  asm volatile("cp.async.wait_group 1;" ::: "memory")
#define CP_WAIT0()  asm volatile("cp.async.wait_group 0;" ::: "memory")

__device__ __forceinline__ uint32_t tf32_of(float x) {
    uint32_t r; asm("cvt.rna.tf32.f32 %0, %1;" : "=r"(r) : "f"(x)); return r;
}
__device__ __forceinline__ void split1(float x, uint32_t& h, uint32_t& l) {
    h = tf32_of(x);
    l = tf32_of(x - __uint_as_float(h));
}

// =====================  small kernels  =====================
__global__ void k_init() {
    int i = blockIdx.x * blockDim.x + threadIdx.x;
    if (i < V_) g_cnt[i] = 0;
    if (i == 0) g_knmax_i = 0;
}

__global__ void k_transpose(const float* __restrict__ z) {
    __shared__ float tile[32][33];
    int b = blockIdx.z, c0 = blockIdx.x << 5, t0 = blockIdx.y << 5;
    int tx = threadIdx.x, ty = threadIdx.y;
#pragma unroll
    for (int j = 0; j < 4; j++)
        tile[ty + 8*j][tx] = z[(b*C_ + c0 + ty + 8*j)*T_ + t0 + tx];
    __syncthreads();
#pragma unroll
    for (int j = 0; j < 4; j++)
        g_hs[(b*T_ + t0 + ty + 8*j)*C_ + c0 + tx] = tile[tx][ty + 8*j];
}

__global__ __launch_bounds__(256) void k_xp(const float* __restrict__ Wp,
                                            const float* __restrict__ bp) {
    __shared__ float w[C_ * H_];
    int tid = threadIdx.x;
    for (int i = tid * 4; i < C_ * H_; i += 1024)
        *(float4*)&w[i] = *(const float4*)&Wp[i];
    __syncthreads();
    int row = blockIdx.x * 256 + tid;
    const float* hsr = g_hs + (size_t)row * C_;
    float acc[8];
#pragma unroll
    for (int j = 0; j < 8; j++) acc[j] = bp[j];
#pragma unroll 4
    for (int k = 0; k < C_; k += 4) {
        float4 hv = *(const float4*)(hsr + k);
        float h[4] = {hv.x, hv.y, hv.z, hv.w};
#pragma unroll
        for (int i = 0; i < 4; i++) {
            float4 wa = *(const float4*)&w[(k + i) * 8];
            float4 wb = *(const float4*)&w[(k + i) * 8 + 4];
            acc[0] += h[i] * wa.x; acc[1] += h[i] * wa.y;
            acc[2] += h[i] * wa.z; acc[3] += h[i] * wa.w;
            acc[4] += h[i] * wb.x; acc[5] += h[i] * wb.y;
            acc[6] += h[i] * wb.z; acc[7] += h[i] * wb.w;
        }
    }
    *(float4*)(g_Xp + row * 8)     = make_float4(acc[0], acc[1], acc[2], acc[3]);
    *(float4*)(g_Xp + row * 8 + 4) = make_float4(acc[4], acc[5], acc[6], acc[7]);
}

// =====================  split-tf32 projection GEMM, cp.async 3-stage  =====================
#define PAW 2560
#define PBW 2176
#define PROJ_SMEM ((3*PAW + 3*PBW) * 4)

__global__ __launch_bounds__(256, 2) void k_proj_mma(
    const float* __restrict__ cb,
    const float* __restrict__ Wq, const float* __restrict__ bq,
    const float* __restrict__ Wk, const float* __restrict__ bk,
    const float* __restrict__ Wv, const float* __restrict__ bv) {
    extern __shared__ __align__(16) unsigned char smraw[];
    const uint32_t smb = (uint32_t)__cvta_generic_to_shared(smraw);

    const float *A, *Bm, *bias; float* C;
    int zid = blockIdx.z;
    if (zid == 0)      { A = g_hs; Bm = Wq; bias = bq; C = g_Xq; }
    else if (zid == 1) { A = cb;   Bm = Wk; bias = bk; C = g_kh; }
    else               { A = cb;   Bm = Wv; bias = bv; C = g_value; }

    const int tid = threadIdx.x;
    const int wid = tid >> 5, lane = tid & 31;
    const int warpM = wid >> 1, warpN = wid & 1;
    const int m0 = blockIdx.y << 7, n0 = blockIdx.x << 7;
    const int ar = tid >> 2, ac = (tid & 3) << 2;
    const int br = tid >> 4, bc = (tid & 15) << 3;
    const int gid = lane >> 2, tig = lane & 3;

    const float* Ag = A + (size_t)(m0 + ar) * C_ + ac;

    const uint32_t dA0 = (uint32_t)(ar * 20 + ac) * 4;
    const uint32_t dA1 = (uint32_t)((ar + 64) * 20 + ac) * 4;
    const uint32_t dB0 = (uint32_t)(br * 136 + bc) * 4;
    const uint32_t dB1 = dB0 + 16;

#define PROJ_ISSUE(s) do { \
    const int _b = (s) % 3; \
    const uint32_t _ab = smb + (uint32_t)_b * (PAW * 4); \
    const uint32_t _bb = smb + (uint32_t)(3 * PAW + _b * PBW) * 4; \
    const float* _A = Ag + (s) * 16; \
    const float* _B = Bm + (size_t)((s) * 16 + br) * 512 + n0 + bc; \
    cp16(_ab + dA0, _A); \
    cp16(_ab + dA1, _A + 64 * C_); \
    cp16(_bb + dB0, _B); \
    cp16(_bb + dB1, _B + 4); \
    CP_COMMIT(); \
} while (0)

    PROJ_ISSUE(0);
    PROJ_ISSUE(1);

    float acc[2][8][4] = {};
    for (int t = 0; t < 32; ++t) {
        const int buf = t % 3;
        if (t + 1 < 32) CP_WAIT1(); else CP_WAIT0();
        __syncthreads();
        if (t + 2 < 32) PROJ_ISSUE(t + 2);

        const float* ASf = (const float*)smraw + buf * PAW;
        const float* BSf = (const float*)smraw + 3 * PAW + buf * PBW;
#pragma unroll
        for (int ks8 = 0; ks8 < 2; ks8++) {
            const int kb = ks8 * 8 + tig;
            uint32_t ah[2][4], al[2][4];
#pragma unroll
            for (int mt = 0; mt < 2; mt++) {
                int r = warpM * 32 + mt * 16 + gid;
                float x0 = ASf[r * 20 + kb];
                float x1 = ASf[(r + 8) * 20 + kb];
                float x2 = ASf[r * 20 + kb + 4];
                float x3 = ASf[(r + 8) * 20 + kb + 4];
                split1(x0, ah[mt][0], al[mt][0]);
                split1(x1, ah[mt][1], al[mt][1]);
                split1(x2, ah[mt][2], al[mt][2]);
                split1(x3, ah[mt][3], al[mt][3]);
            }
#pragma unroll
            for (int ntp = 0; ntp < 4; ntp++) {
                const int nt0 = ntp * 2, nt1 = nt0 + 1;
                const int c0 = warpN * 64 + nt0 * 8 + gid;
                const int c1 = c0 + 8;
                float y00 = BSf[kb * 136 + c0];
                float y01 = BSf[(kb + 4) * 136 + c0];
                float y10 = BSf[kb * 136 + c1];
                float y11 = BSf[(kb + 4) * 136 + c1];
                uint32_t bh00, bl00, bh01, bl01, bh10, bl10, bh11, bl11;
                split1(y00, bh00, bl00);
                split1(y01, bh01, bl01);
                split1(y10, bh10, bl10);
                split1(y11, bh11, bl11);
                // term-major: same-acc reuse spacing = 4 MMAs
                // (per-acc term order hh, hl, lh preserved -> bit-identical sums)
                MMA_TF32(acc[0][nt0], ah[0], bh00, bh01);
                MMA_TF32(acc[1][nt0], ah[1], bh00, bh01);
                MMA_TF32(acc[0][nt1], ah[0], bh10, bh11);
                MMA_TF32(acc[1][nt1], ah[1], bh10, bh11);
                MMA_TF32(acc[0][nt0], ah[0], bl00, bl01);
                MMA_TF32(acc[1][nt0], ah[1], bl00, bl01);
                MMA_TF32(acc[0][nt1], ah[0], bl10, bl11);
                MMA_TF32(acc[1][nt1], ah[1], bl10, bl11);
                MMA_TF32(acc[0][nt0], al[0], bh00, bh01);
                MMA_TF32(acc[1][nt0], al[1], bh00, bh01);
                MMA_TF32(acc[0][nt1], al[0], bh10, bh11);
                MMA_TF32(acc[1][nt1], al[1], bh10, bh11);
            }
        }
        __syncthreads();
    }

#pragma unroll
    for (int mt = 0; mt < 2; mt++) {
#pragma unroll
        for (int nt = 0; nt < 8; nt++) {
            int row = m0 + warpM * 32 + mt * 16 + gid;
            int col = n0 + warpN * 64 + nt * 8 + 2 * tig;
            float b0 = bias[col], b1 = bias[col + 1];
            float2 v0 = make_float2(acc[mt][nt][0] + b0, acc[mt][nt][1] + b1);
            float2 v1 = make_float2(acc[mt][nt][2] + b0, acc[mt][nt][3] + b1);
            *(float2*)(C + (size_t)row * C_ + col)       = v0;
            *(float2*)(C + (size_t)(row + 8) * C_ + col) = v1;
        }
    }
#undef PROJ_ISSUE
}

// =====================  fused rmsnorm + combine (khnorm | qfull | qrest)  =====================
__device__ __forceinline__ float head_rms_scale(float x, int d, float* ws) {
    float s = x * x;
#pragma unroll
    for (int o = 16; o; o >>= 1) s += __shfl_xor_sync(0xffffffffu, s, o);
    if ((d & 31) == 0) ws[d >> 5] = s;
    __syncthreads();
    int h = d >> 6;
    float tot = ws[2*h] + ws[2*h + 1];
    return rsqrtf(tot * (1.0f/64.0f) + 1e-5f);
}

__device__ __forceinline__ float block_sum_sq(float v, int d, float* s2) {
    float s = v * v;
#pragma unroll
    for (int o = 16; o; o >>= 1) s += __shfl_xor_sync(0xffffffffu, s, o);
    if ((d & 31) == 0) s2[d >> 5] = s;
    __syncthreads();
    float tot = 0.0f;
    if (d == 0) {
#pragma unroll
        for (int i = 0; i < 16; i++) tot += s2[i];
    }
    return tot;
}

__global__ void k_norms(const float* __restrict__ gq, const float* __restrict__ gk) {
    __shared__ float ws[16];
    __shared__ float s2[16];
    const int b = blockIdx.x;
    const int d = threadIdx.x;
    const int h = d >> 6;

    if (b < V_) {                      // khnorm
        int row = b;
        float x = g_kh[(size_t)row*C_ + d];
        float r = head_rms_scale(x, d, ws);
        float v = x * r * gk[d & 63];
        g_kh[(size_t)row*C_ + d] = v;
        g_Kh[(size_t)row*C_ + d] = __float2bfloat16(v);
        __syncthreads();
        float n2 = block_sum_sq(v, d, s2);
        if (d == 0) atomicMax(&g_knmax_i, __float_as_int(sqrtf(n2)));
    } else if (b < V_ + MFULL) {       // qfull
        int row = b - V_;
        float x = g_Xq[(size_t)row*C_ + d];
        float r = head_rms_scale(x, d, ws);
        float c = g_Xp[row*H_ + h];
        float v = x * r * gq[d & 63] * c * COMB_SCALE;
        g_Q[(size_t)row*C_ + d] = v;
        g_Qh[(size_t)row*C_ + d] = __float2bfloat16(v);
        __syncthreads();
        float n2 = block_sum_sq(v, d, s2);
        if (d == 0) g_qnorm[row] = sqrtf(n2);
    } else {                           // qrest
        int row = b - V_ - MFULL;
        int fr = (row >> 8) * T_ + (row & 255) * 4;
        const float* p = g_Xq + (size_t)fr*C_ + d;
        float x = 0.25f * (p[0] + p[C_] + p[2*C_] + p[3*C_]);
        float r = head_rms_scale(x, d, ws);
        const float* pc = g_Xp + fr*H_ + h;
        float c = 0.25f * (pc[0] + pc[H_] + pc[2*H_] + pc[3*H_]);
        float v = x * r * gq[d & 63] * c * COMB_SCALE;
        g_Q[(size_t)(MFULL + row)*C_ + d] = v;
        g_Qh[(size_t)(MFULL + row)*C_ + d] = __float2bfloat16(v);
        __syncthreads();
        float n2 = block_sum_sq(v, d, s2);
        if (d == 0) g_qnorm[MFULL + row] = sqrtf(n2);
    }
}

// =====================  bf16 logits GEMM, cp.async 3-stage  =====================
#define LAW 2560
#define LOG_SMEM ((6 * LAW) * 4)

__global__ __launch_bounds__(256, 2) void k_logits_mma() {
    extern __shared__ __align__(16) unsigned char smraw[];
    const uint32_t smb = (uint32_t)__cvta_generic_to_shared(smraw);
    const int tid = threadIdx.x;
    const int wid = tid >> 5, lane = tid & 31;
    const int warpM = wid >> 1, warpN = wid & 1;
    const int m0 = blockIdx.y << 7, n0 = blockIdx.x << 7;
    const int gid = lane >> 2, tig = lane & 3;
    const int row = tid >> 1, hf = tid & 1;

    const char* Ag = (const char*)(g_Qh + (size_t)(m0 + row) * C_) + hf * 32;
    const char* Bg = (const char*)(g_Kh + (size_t)(n0 + row) * C_) + hf * 32;
    const uint32_t dT = (uint32_t)(row * 20 + hf * 8) * 4;

#define LOG_ISSUE(s) do { \
    const int _b = (s) % 3; \
    const uint32_t _a = smb + (uint32_t)(_b * LAW) * 4 + dT; \
    const uint32_t _bb = smb + (uint32_t)((3 + _b) * LAW) * 4 + dT; \
    cp16(_a,       Ag + (s) * 64); \
    cp16(_a + 16,  Ag + (s) * 64 + 16); \
    cp16(_bb,      Bg + (s) * 64); \
    cp16(_bb + 16, Bg + (s) * 64 + 16); \
    CP_COMMIT(); \
} while (0)

    LOG_ISSUE(0);
    LOG_ISSUE(1);

    float acc[2][8][4] = {};
    for (int t = 0; t < 16; ++t) {
        const int buf = t % 3;
        if (t + 1 < 16) CP_WAIT1(); else CP_WAIT0();
        __syncthreads();
        if (t + 2 < 16) LOG_ISSUE(t + 2);

        const uint32_t* As = (const uint32_t*)smraw + buf * LAW;
        const uint32_t* Bs = (const uint32_t*)smraw + (3 + buf) * LAW;
#pragma unroll
        for (int ku = 0; ku < 16; ku += 8) {
            uint32_t af[2][4];
#pragma unroll
            for (int mt = 0; mt < 2; mt++) {
                int r = warpM * 32 + mt * 16 + gid;
                af[mt][0] = As[r * 20 + ku + tig];
                af[mt][1] = As[(r + 8) * 20 + ku + tig];
                af[mt][2] = As[r * 20 + ku + tig + 4];
                af[mt][3] = As[(r + 8) * 20 + ku + tig + 4];
            }
#pragma unroll
            for (int nt = 0; nt < 8; nt++) {
                int c = warpN * 64 + nt * 8 + gid;
                uint32_t b0 = Bs[c * 20 + ku + tig];
                uint32_t b1 = Bs[c * 20 + ku + tig + 4];
                MMA_BF16(acc[0][nt], af[0], b0, b1);
                MMA_BF16(acc[1][nt], af[1], b0, b1);
            }
        }
        __syncthreads();
    }

#pragma unroll
    for (int mt = 0; mt < 2; mt++) {
#pragma unroll
        for (int nt = 0; nt < 8; nt++) {
            int r = m0 + warpM * 32 + mt * 16 + gid;
            int col = n0 + warpN * 64 + nt * 8 + 2 * tig;
            __nv_bfloat162 p0 = __floats2bfloat162_rn(acc[mt][nt][0], acc[mt][nt][1]);
            __nv_bfloat162 p1 = __floats2bfloat162_rn(acc[mt][nt][2], acc[mt][nt][3]);
            *(__nv_bfloat162*)(g_logitsh + (size_t)r * V_ + col)       = p0;
            *(__nv_bfloat162*)(g_logitsh + (size_t)(r + 8) * V_ + col) = p1;
        }
    }
#undef LOG_ISSUE
}

// =====================  margin select + warp-parallel exact rescore (+hist)  =====================
__global__ __launch_bounds__(256, 4) void k_select() {
    __shared__ float s_red[8];
    __shared__ float s_max;
    __shared__ int   s_cnt;
    __shared__ int   s_cand[128];
    __shared__ float s_cval[128];
    __shared__ float sq[C_];
    const int row = blockIdx.x;
    const int tid = threadIdx.x;
    const int wid = tid >> 5, lane = tid & 31;
    const uint4* L = (const uint4*)(g_logitsh + (size_t)row * V_);

    *(float2*)&sq[tid*2] = *(const float2*)(g_Q + (size_t)row * C_ + tid*2);

    uint4 u0 = L[tid], u1 = L[tid + 256];
    float vals[16];
    {
        uint32_t w[8] = {u0.x,u0.y,u0.z,u0.w, u1.x,u1.y,u1.z,u1.w};
#pragma unroll
        for (int q = 0; q < 8; q++) {
            float2 f = __bfloat1622float2(*(__nv_bfloat162*)&w[q]);
            vals[q*2] = f.x; vals[q*2+1] = f.y;
        }
    }
    float vmax = -1e30f;
#pragma unroll
    for (int q = 0; q < 16; q++) vmax = fmaxf(vmax, vals[q]);
#pragma unroll
    for (int o = 16; o; o >>= 1) vmax = fmaxf(vmax, __shfl_xor_sync(0xffffffffu, vmax, o));
    if (lane == 0) s_red[wid] = vmax;
    if (tid == 0) s_cnt = 0;
    __syncthreads();
    if (tid == 0) {
        float m = s_red[0];
#pragma unroll
        for (int i = 1; i < 8; i++) m = fmaxf(m, s_red[i]);
        s_max = m;
    }
    __syncthreads();
    const float kn = __int_as_float(g_knmax_i);
    const float margin = 0.022f * g_qnorm[row] * kn + 1e-6f;
    const float thr = s_max - margin;

#pragma unroll
    for (int q = 0; q < 16; q++) {
        if (vals[q] >= thr) {
            int base = (q < 8) ? (tid * 8 + q) : (2048 + tid * 8 + (q - 8));
            int p = atomicAdd(&s_cnt, 1);
            if (p < 128) s_cand[p] = base;
        }
    }
    __syncthreads();
    int cnt = min(s_cnt, 128);

    for (int c = wid; c < cnt; c += 8) {
        int n = s_cand[c];
        const float* kr = g_kh + (size_t)n * C_;
        float p = 0.0f;
#pragma unroll
        for (int i = 0; i < 16; i++) p += sq[i*32 + lane] * kr[i*32 + lane];
#pragma unroll
        for (int o = 16; o; o >>= 1) p += __shfl_xor_sync(0xffffffffu, p, o);
        if (lane == 0) s_cval[c] = p;
    }
    __syncthreads();
    if (tid == 0) {
        float best_v = -1e30f;
        int best_n = 1 << 30;
        for (int c = 0; c < cnt; c++) {
            float v = s_cval[c];
            int n = s_cand[c];
            if (v > best_v || (v == best_v && n < best_n)) { best_v = v; best_n = n; }
        }
        g_idx[row] = best_n;
        if (row < MFULL) atomicAdd(&g_cnt[best_n], 1);
    }
}

// =====================  output kernels  =====================
__global__ void k_out(float* __restrict__ out) {
    int idx = blockIdx.x * blockDim.x + threadIdx.x;
    if (idx >= ZHAT_ELEMS) return;
    int t = idx & (T_ - 1);
    int d = (idx >> 10) & 511;
    int b = idx >> 19;
    float pos = (t + 0.5f) * ((float)Q_ / (float)T_) - 0.5f;
    pos = fminf(fmaxf(pos, 0.0f), (float)(Q_ - 1));
    int i0 = (int)pos;
    int i1 = min(i0 + 1, Q_ - 1);
    float w = pos - (float)i0;
    int n0 = g_idx[MFULL + b*Q_ + i0];
    int n1 = g_idx[MFULL + b*Q_ + i1];
    out[idx] = (1.0f - w) * g_value[(size_t)n0*C_ + d] + w * g_value[(size_t)n1*C_ + d];
}

__global__ void k_perp(float* __restrict__ out) {
    __shared__ float sm_[1024];
    int tid = threadIdx.x;
    float s = 0.0f;
    for (int j = tid; j < V_; j += 1024) {
        float p = (float)g_cnt[j] * (1.0f / 4096.0f);
        s += p * logf(p + 1e-7f);
    }
    sm_[tid] = s;
    __syncthreads();
    for (int o = 512; o; o >>= 1) {
        if (tid < o) sm_[tid] += sm_[tid + o];
        __syncthreads();
    }
    if (tid == 0) out[ZHAT_ELEMS] = expf(-sm_[0]);
}

// ---------------------------------------------------------------------------
extern "C" void kernel_launch(void* const* d_in, const int* in_sizes, int n_in,
                              void* d_out, int out_size) {
    const float* z        = (const float*)d_in[0];
    const float* codebook = (const float*)d_in[2];
    const float* Wq = (const float*)d_in[3];
    const float* bq = (const float*)d_in[4];
    const float* Wk = (const float*)d_in[5];
    const float* bk = (const float*)d_in[6];
    const float* Wv = (const float*)d_in[7];
    const float* bv = (const float*)d_in[8];
    const float* Wp = (const float*)d_in[9];
    const float* bp = (const float*)d_in[10];
    const float* gq = (const float*)d_in[11];
    const float* gk = (const float*)d_in[12];
    float* out = (float*)d_out;

    cudaFuncSetAttribute(k_proj_mma, cudaFuncAttributeMaxDynamicSharedMemorySize, PROJ_SMEM);
    cudaFuncSetAttribute(k_logits_mma, cudaFuncAttributeMaxDynamicSharedMemorySize, LOG_SMEM);

    k_transpose<<<dim3(16, 32, 4), dim3(32, 8)>>>(z);           // 1
    k_xp<<<16, 256>>>(Wp, bp);                                  // 2
    k_init<<<(V_ + 255)/256, 256>>>();                          // 3
    k_proj_mma<<<dim3(4, 32, 3), 256, PROJ_SMEM>>>(codebook, Wq, bq, Wk, bk, Wv, bv); // 4 (profiled)

    k_norms<<<V_ + MFULL + MREST, 512>>>(gq, gk);               // fused khnorm/qfull/qrest

    k_logits_mma<<<dim3(V_/128, MTOT/128), 256, LOG_SMEM>>>();
    k_select<<<MTOT, 256>>>();

    k_out<<<(ZHAT_ELEMS + 255)/256, 256>>>(out);
    k_perp<<<1, 1024>>>(out);
}